// round 4
// baseline (speedup 1.0000x reference)
#include <cuda_runtime.h>
#include <cuda_bf16.h>
#include <math.h>
#include <cstdint>

#define NQ   24576        // R*S
#define SS   48
#define MP   4096
#define LDX  512          // padded feature stride (D0=511 + 1 zero col)
#define D0   511
#define HD   256

// ---------------- scratch (static device globals; no runtime alloc) ----------
// activations stored pre-split as bf16 hi/lo matrices
__device__ __nv_bfloat16 g_Xh[NQ * LDX], g_Xl[NQ * LDX];
__device__ __nv_bfloat16 g_h1h[NQ * HD], g_h1l[NQ * HD];
__device__ __nv_bfloat16 g_h2h[NQ * HD], g_h2l[NQ * HD];
__device__ float         g_fin[NQ * HD];
// pre-split weights (bf16 hi/lo), W0 padded K 511 -> 512
__device__ __nv_bfloat16 g_w0h[HD * 512], g_w0l[HD * 512];
__device__ __nv_bfloat16 g_w1h[HD * HD],  g_w1l[HD * HD];
__device__ __nv_bfloat16 g_w2h[HD * HD],  g_w2l[HD * HD];

// ============================ helpers ========================================
__device__ __forceinline__ uint32_t smem_u32(const void* p) {
    uint32_t a;
    asm("{ .reg .u64 t; cvta.to.shared.u64 t, %1; cvt.u32.u64 %0, t; }"
        : "=r"(a) : "l"(p));
    return a;
}
__device__ __forceinline__ void ldm_x4(uint32_t* r, uint32_t addr) {
    asm volatile("ldmatrix.sync.aligned.m8n8.x4.shared.b16 {%0,%1,%2,%3}, [%4];"
        : "=r"(r[0]), "=r"(r[1]), "=r"(r[2]), "=r"(r[3]) : "r"(addr));
}
__device__ __forceinline__ void ldm_x2(uint32_t* r, uint32_t addr) {
    asm volatile("ldmatrix.sync.aligned.m8n8.x2.shared.b16 {%0,%1}, [%2];"
        : "=r"(r[0]), "=r"(r[1]) : "r"(addr));
}
__device__ __forceinline__ void mma_bf16(float* d, const uint32_t* a, const uint32_t* b) {
    asm volatile("mma.sync.aligned.m16n8k16.row.col.f32.bf16.bf16.f32 "
        "{%0,%1,%2,%3}, {%4,%5,%6,%7}, {%8,%9}, {%0,%1,%2,%3};"
        : "+f"(d[0]), "+f"(d[1]), "+f"(d[2]), "+f"(d[3])
        : "r"(a[0]), "r"(a[1]), "r"(a[2]), "r"(a[3]), "r"(b[0]), "r"(b[1]));
}
#define CP16(dst, src) \
    asm volatile("cp.async.cg.shared.global [%0], [%1], 16;" :: "r"(dst), "l"(src) : "memory")
#define CP_COMMIT() asm volatile("cp.async.commit_group;" ::: "memory")
#define CP_WAIT1()  asm volatile("cp.async.wait_group 1;" ::: "memory")

__device__ __forceinline__ uint32_t swz(uint32_t off) {
    return off ^ ((off >> 3) & 0x70);
}
__device__ __forceinline__ int cell_of(float x, float y, float z) {
    int cx = min(max(__float2int_rd(x * 10.0f), 0), 9);
    int cy = min(max(__float2int_rd(y * 10.0f), 0), 9);
    int cz = min(max(__float2int_rd(z * 10.0f), 0), 9);
    return cx + 10 * cy + 100 * cz;
}
// split-write: v -> bf16 hi + bf16 lo at idx
__device__ __forceinline__ void wsplit(__nv_bfloat16* H, __nv_bfloat16* L,
                                       size_t idx, float v) {
    __nv_bfloat16 h = __float2bfloat16(v);
    H[idx] = h;
    L[idx] = __float2bfloat16(v - __bfloat162float(h));
}
__device__ __forceinline__ void store2_split(__nv_bfloat16* H, __nv_bfloat16* L,
                                             size_t idx, float a, float b) {
    __nv_bfloat16 ha = __float2bfloat16(a), hb = __float2bfloat16(b);
    __nv_bfloat16 la = __float2bfloat16(a - __bfloat162float(ha));
    __nv_bfloat16 lb = __float2bfloat16(b - __bfloat162float(hb));
    uint32_t hw = (uint32_t)__bfloat16_as_ushort(ha) | ((uint32_t)__bfloat16_as_ushort(hb) << 16);
    uint32_t lw = (uint32_t)__bfloat16_as_ushort(la) | ((uint32_t)__bfloat16_as_ushort(lb) << 16);
    *(uint32_t*)(H + idx) = hw;
    *(uint32_t*)(L + idx) = lw;
}

// ---------------- posenc via double-angle recurrence ---------------------------
template<int C, int F>
__device__ __forceinline__ void posenc_write(__nv_bfloat16* H, __nv_bfloat16* L,
                                             int off, const float* v)
{
    float s[C], c[C];
    #pragma unroll
    for (int i = 0; i < C; i++) { wsplit(H, L, off + i, v[i]); sincosf(v[i], &s[i], &c[i]); }
    #pragma unroll
    for (int f = 0; f < F; f++) {
        #pragma unroll
        for (int i = 0; i < C; i++) {
            wsplit(H, L, off + C + f*2*C + i,     s[i]);
            wsplit(H, L, off + C + f*2*C + C + i, c[i]);
        }
        if (f + 1 < F) {
            #pragma unroll
            for (int i = 0; i < C; i++) {
                float ns = 2.0f * s[i] * c[i];
                float nc = fmaf(-2.0f * s[i], s[i], 1.0f);
                s[i] = ns; c[i] = nc;
            }
        }
    }
}

// ---------------- feature kernel: per-CTA grid build + ball query + embeddings -
// dyn smem: spts float4[4096] | sstart int[1001] | scur int[1000] | spartial int[128]
#define OF_START (MP * 16)
#define OF_CUR   (OF_START + 1004 * 4)
#define OF_PART  (OF_CUR + 1000 * 4)
#define FSMEM    (OF_PART + 128 * 4)

__global__ void __launch_bounds__(128)
feature_kernel(const float* __restrict__ points,
               const float* __restrict__ normals,
               const float* __restrict__ pp,
               const float* __restrict__ rays,
               const float* __restrict__ ro)
{
    extern __shared__ char fsm[];
    float4* spts    = (float4*)fsm;
    int*    sstart  = (int*)(fsm + OF_START);
    int*    scur    = (int*)(fsm + OF_CUR);
    int*    spart   = (int*)(fsm + OF_PART);

    const int tid = threadIdx.x;

    // ---- per-CTA grid build (redundant but parallel across CTAs) ----
    for (int i = tid; i < 1000; i += 128) scur[i] = 0;
    __syncthreads();
    for (int i = tid; i < MP; i += 128) {
        float x = pp[3*i], y = pp[3*i+1], z = pp[3*i+2];
        atomicAdd(&scur[cell_of(x, y, z)], 1);
    }
    __syncthreads();
    // 2-level exclusive scan of 1000 counts (8 cells/thread, 125 active)
    int cnts[8]; int lsum = 0;
    if (tid < 125) {
        #pragma unroll
        for (int j = 0; j < 8; j++) { cnts[j] = scur[tid*8 + j]; lsum += cnts[j]; }
    }
    spart[tid] = lsum;
    __syncthreads();
    #pragma unroll
    for (int d = 1; d < 128; d <<= 1) {
        int v = (tid >= d) ? spart[tid - d] : 0;
        __syncthreads();
        spart[tid] += v;
        __syncthreads();
    }
    int excl = spart[tid] - lsum;
    if (tid < 125) {
        int run = excl;
        #pragma unroll
        for (int j = 0; j < 8; j++) { sstart[tid*8 + j] = run; run += cnts[j]; }
    }
    if (tid == 0) sstart[1000] = MP;
    __syncthreads();
    for (int i = tid; i < 1000; i += 128) scur[i] = sstart[i];
    __syncthreads();
    for (int i = tid; i < MP; i += 128) {
        float x = pp[3*i], y = pp[3*i+1], z = pp[3*i+2];
        int c = cell_of(x, y, z);
        int pos = atomicAdd(&scur[c], 1);
        spts[pos] = make_float4(x, y, z, __int_as_float(i));
    }
    __syncthreads();

    // ---- ball query ----
    const int gid = blockIdx.x * 128 + tid;
    const float qx = points[3*gid+0], qy = points[3*gid+1], qz = points[3*gid+2];

    const float R2  = (float)(0.1 * 0.1);   // fp64-computed threshold bits
    const float RAD = 0.1f;

    int cand[64];
    int cnt = 0;
    {
        int cx = min(max(__float2int_rd(qx * 10.0f), 0), 9);
        int cy = min(max(__float2int_rd(qy * 10.0f), 0), 9);
        int cz = min(max(__float2int_rd(qz * 10.0f), 0), 9);
        int x0 = max(cx-1,0), x1 = min(cx+1,9);
        int y0 = max(cy-1,0), y1 = min(cy+1,9);
        int z0 = max(cz-1,0), z1 = min(cz+1,9);
        for (int zz = z0; zz <= z1; zz++)
        for (int yy = y0; yy <= y1; yy++)
        for (int xx = x0; xx <= x1; xx++) {
            int c  = xx + 10*yy + 100*zz;
            int s0 = sstart[c], s1 = sstart[c+1];
            for (int i = s0; i < s1; i++) {
                float4 p = spts[i];
                float dx = p.x - qx, dy = p.y - qy, dz = p.z - qz;
                float d2 = dx*dx + dy*dy + dz*dz;
                if (d2 < R2 && cnt < 64)
                    cand[cnt++] = (__float_as_int(p.w) << 12) | i;
            }
        }
    }
    // sort ascending by original index -> first-k-by-index semantics
    for (int i = 1; i < cnt; i++) {
        int v = cand[i], j = i - 1;
        while (j >= 0 && cand[j] > v) { cand[j+1] = cand[j]; j--; }
        cand[j+1] = v;
    }
    const int kk = min(cnt, 16);
    float nx[16], ny[16], nz[16], nd[16];
    for (int k = 0; k < kk; k++) {
        float4 p = spts[cand[k] & 4095];
        float dx = p.x - qx, dy = p.y - qy, dz = p.z - qz;
        nx[k] = p.x; ny[k] = p.y; nz[k] = p.z;
        nd[k] = dx*dx + dy*dy + dz*dz;
    }

    float qn = sqrtf(qx*qx + qy*qy + qz*qz);
    float t0 = qn / RAD;
    float w0 = fmaxf(1.0f - t0*t0*t0, 0.0f);

    float density = 0.0f, smx = 0.0f, smy = 0.0f, smz = 0.0f;
    for (int k = 0; k < 16; k++) {
        if (k < kk) {
            float dn = sqrtf(nd[k]);
            float tt = dn / RAD;
            float w  = fmaxf(1.0f - tt*tt*tt, 0.0f);
            density += w;
            smx += w * nx[k]; smy += w * ny[k]; smz += w * nz[k];
        } else {
            density += w0;
        }
    }

    int   num_nn = 0;
    float sdx = 0.0f, sdy = 0.0f, sdz = 0.0f;
    for (int k = 0; k < kk; k++) {
        if (nd[k] != 0.0f) {
            num_nn++;
            sdx += nx[k] - qx; sdy += ny[k] - qy; sdz += nz[k] - qz;
        }
    }
    float inv = (float)num_nn + 1e-12f;
    float mx = sdx / inv, my = sdy / inv, mz = sdz / inv;
    float vx = 0.0f, vy = 0.0f, vz = 0.0f;
    for (int k = 0; k < kk; k++) {
        if (nd[k] != 0.0f) {
            float ex = (nx[k] - qx) - mx;
            float ey = (ny[k] - qy) - my;
            float ez = (nz[k] - qz) - mz;
            vx += ex*ex; vy += ey*ey; vz += ez*ez;
        }
    }
    vx /= inv; vy /= inv; vz /= inv;

    float dinv = density + 1e-12f;
    float spx = smx / dinv, spy = smy / dinv, spz = smz / dinv;
    float dirx = spx - ro[0], diry = spy - ro[1], dirz = spz - ro[2];
    float dl = sqrtf(dirx*dirx + diry*diry + dirz*dirz);
    dirx /= dl; diry /= dl; dirz /= dl;

    __nv_bfloat16* H = g_Xh + (size_t)gid * LDX;
    __nv_bfloat16* L = g_Xl + (size_t)gid * LDX;
    float q3[3]  = {qx, qy, qz};       posenc_write<3,10>(H, L, 0,   q3);
    float d1[1]  = {density};          posenc_write<1,4> (H, L, 63,  d1);
    float sp3[3] = {spx, spy, spz};    posenc_write<3,10>(H, L, 72,  sp3);
    float v3[3]  = {vx, vy, vz};       posenc_write<3,10>(H, L, 135, v3);
    int r = gid / SS;
    float rd[3]  = {rays[6*r+3], rays[6*r+4], rays[6*r+5]};
    posenc_write<3,4>(H, L, 198, rd);
    float dd[3]  = {dirx, diry, dirz}; posenc_write<3,4> (H, L, 225, dd);
    wsplit(H, L, 252, normals[3*gid+0]);
    wsplit(H, L, 253, normals[3*gid+1]);
    wsplit(H, L, 254, normals[3*gid+2]);
    H[511] = __float2bfloat16(0.0f);
    L[511] = __float2bfloat16(0.0f);
}

// ---------------- split-copy of feature_vectors into X[:,255:511] -------------
__global__ void __launch_bounds__(256)
copy_fv_kernel(const float* __restrict__ fv)
{
    int i = blockIdx.x * blockDim.x + threadIdx.x;
    if (i < NQ * HD) {
        int row = i >> 8;
        int col = i & 255;
        wsplit(g_Xh, g_Xl, (size_t)row * LDX + 255 + col, fv[i]);
    }
}

// ---------------- weight split: fp32 -> bf16 hi/lo, K padded to Kp -------------
__global__ void __launch_bounds__(256)
convW_kernel(const float* __restrict__ W, int N, int K, int Kp,
             __nv_bfloat16* __restrict__ Wh, __nv_bfloat16* __restrict__ Wl)
{
    int i = blockIdx.x * 256 + threadIdx.x;
    if (i >= N * Kp) return;
    int n = i / Kp, k = i - n * Kp;
    float v = (k < K) ? W[(size_t)n * K + k] : 0.0f;
    __nv_bfloat16 h = __float2bfloat16(v);
    float r = v - __bfloat162float(h);
    Wh[i] = h;
    Wl[i] = __float2bfloat16(r);
}

// ================= warp-mma split-bf16 GEMM: C = relu(A @ W^T + b) =============
// Ah/Al bf16 [NQ, lda]; Wh/Wl bf16 [256, Kp].
// Output: mode 0 -> CH/CL bf16 split; mode 1 -> Cf fp32.
// Block tile 128m x 128n x 32k, 8 warps (4m x 2n), cp.async 3-stage pipeline.
#define BM 128
#define BN 128
#define STAGE 32768            // A(hi|lo) 16KB + B(hi|lo) 16KB per stage
#define NSTAGE 3
#define GSMEM (NSTAGE * STAGE + 512)

__device__ __forceinline__ void stage_tile(
    uint32_t sb,
    const __nv_bfloat16* __restrict__ Ah, const __nv_bfloat16* __restrict__ Al, int lda,
    const __nv_bfloat16* __restrict__ Bh, const __nv_bfloat16* __restrict__ Bl, int ldb,
    int rowBase, int colBase, int k0, int tid)
{
    const int r = tid >> 2, c = tid & 3;
    #pragma unroll
    for (int i = 0; i < 2; i++) {
        int row = r + i * 64;
        size_t gi = (size_t)(rowBase + row) * lda + k0 + c * 8;
        uint32_t off = (uint32_t)(row << 7) + (uint32_t)(c << 4);
        CP16(sb + swz(off),      Ah + gi);
        CP16(sb + swz(off + 64), Al + gi);
    }
    #pragma unroll
    for (int i = 0; i < 2; i++) {
        int row = r + i * 64;
        size_t gi = (size_t)(colBase + row) * ldb + k0 + c * 8;
        uint32_t off = (uint32_t)(row << 7) + (uint32_t)(c << 4);
        CP16(sb + 16384 + swz(off),      Bh + gi);
        CP16(sb + 16384 + swz(off + 64), Bl + gi);
    }
}

__global__ void __launch_bounds__(256, 2)
mma_gemm_kernel(const __nv_bfloat16* __restrict__ Ah,
                const __nv_bfloat16* __restrict__ Al, int lda,
                const __nv_bfloat16* __restrict__ Bh,
                const __nv_bfloat16* __restrict__ Bl, int Kp,
                const float* __restrict__ bias,
                __nv_bfloat16* __restrict__ CH,
                __nv_bfloat16* __restrict__ CL,
                float* __restrict__ Cf,
                int outMode)
{
    extern __shared__ char gsm[];
    const uint32_t sbase = smem_u32(gsm);
    float* sbias = (float*)(gsm + NSTAGE * STAGE);

    const int tid  = threadIdx.x;
    const int wid  = tid >> 5;
    const int lane = tid & 31;
    const int wm   = wid & 3;          // 4 warps in m
    const int wn   = wid >> 2;         // 2 warps in n
    const int rowBase = blockIdx.x * BM;
    const int colBase = blockIdx.y * BN;

    if (tid < 128) sbias[tid] = bias[colBase + tid];

    float acc[2][8][4];
    #pragma unroll
    for (int mi = 0; mi < 2; mi++)
        #pragma unroll
        for (int ni = 0; ni < 8; ni++)
            #pragma unroll
            for (int e = 0; e < 4; e++) acc[mi][ni][e] = 0.0f;

    const int T = Kp / 32;

    // prologue: stage tiles 0,1
    stage_tile(sbase, Ah, Al, lda, Bh, Bl, Kp, rowBase, colBase, 0, tid);
    CP_COMMIT();
    if (T > 1)
        stage_tile(sbase + STAGE, Ah, Al, lda, Bh, Bl, Kp, rowBase, colBase, 32, tid);
    CP_COMMIT();

    for (int t = 0; t < T; t++) {
        CP_WAIT1();
        __syncthreads();

        // ---- compute tile t ----
        const uint32_t aB = sbase + (uint32_t)(t % NSTAGE) * STAGE;
        const uint32_t bB = aB + 16384;
        #pragma unroll
        for (int ks = 0; ks < 2; ks++) {
            uint32_t bf[8][2][2];
            #pragma unroll
            for (int ni = 0; ni < 8; ni++)
                #pragma unroll
                for (int h = 0; h < 2; h++) {
                    int r  = wn * 64 + ni * 8 + (lane & 7);
                    int ch = h * 4 + ks * 2 + ((lane >> 3) & 1);
                    ldm_x2(bf[ni][h], bB + swz((uint32_t)(r << 7) + (uint32_t)(ch << 4)));
                }
            #pragma unroll
            for (int mi = 0; mi < 2; mi++) {
                uint32_t afh[4], afl[4];
                {
                    int r  = wm * 32 + mi * 16 + (lane & 15);
                    int c0 = ks * 2 + (lane >> 4);
                    ldm_x4(afh, aB + swz((uint32_t)(r << 7) + (uint32_t)(c0 << 4)));
                    ldm_x4(afl, aB + swz((uint32_t)(r << 7) + (uint32_t)((c0 + 4) << 4)));
                }
                #pragma unroll
                for (int ni = 0; ni < 8; ni++) {
                    mma_bf16(acc[mi][ni], afh, bf[ni][0]);  // Ah*Bh
                    mma_bf16(acc[mi][ni], afh, bf[ni][1]);  // Ah*Bl
                    mma_bf16(acc[mi][ni], afl, bf[ni][0]);  // Al*Bh
                }
            }
        }
        __syncthreads();

        // ---- stage tile t+2 ----
        if (t + 2 < T)
            stage_tile(sbase + (uint32_t)((t + 2) % NSTAGE) * STAGE,
                       Ah, Al, lda, Bh, Bl, Kp, rowBase, colBase, (t + 2) * 32, tid);
        CP_COMMIT();
    }

    // ---- epilogue: bias + relu + store (split bf16 or fp32) ----
    #pragma unroll
    for (int mi = 0; mi < 2; mi++)
        #pragma unroll
        for (int ni = 0; ni < 8; ni++) {
            int m  = rowBase + wm * 32 + mi * 16 + (lane >> 2);
            int nl = wn * 64 + ni * 8 + ((lane & 3) << 1);
            int n  = colBase + nl;
            float b0 = sbias[nl], b1 = sbias[nl + 1];
            float v00 = fmaxf(acc[mi][ni][0] + b0, 0.0f);
            float v01 = fmaxf(acc[mi][ni][1] + b1, 0.0f);
            float v10 = fmaxf(acc[mi][ni][2] + b0, 0.0f);
            float v11 = fmaxf(acc[mi][ni][3] + b1, 0.0f);
            if (outMode == 0) {
                store2_split(CH, CL, (size_t)m * HD + n,       v00, v01);
                store2_split(CH, CL, (size_t)(m + 8) * HD + n, v10, v11);
            } else {
                *(float2*)(Cf + (size_t)m * HD + n)       = make_float2(v00, v01);
                *(float2*)(Cf + (size_t)(m + 8) * HD + n) = make_float2(v10, v11);
            }
        }
}

// ---------------- final layer: out = sigmoid(X @ W3^T + b3), W3 [3,256] --------
__global__ void __launch_bounds__(256)
final_kernel(const float* __restrict__ Xin,
             const float* __restrict__ W3,
             const float* __restrict__ b3,
             float* __restrict__ out)
{
    __shared__ float w[3][256];
    __shared__ float bb[3];
    const int tid = threadIdx.x;
    for (int i = tid; i < 768; i += 256) w[i >> 8][i & 255] = W3[i];
    if (tid < 3) bb[tid] = b3[tid];
    __syncthreads();

    const int warp = tid >> 5, lane = tid & 31;
    const int row = blockIdx.x * 8 + warp;
    const float* xr = Xin + (size_t)row * HD;

    float a0 = 0.0f, a1 = 0.0f, a2 = 0.0f;
    #pragma unroll
    for (int i = lane; i < HD; i += 32) {
        float xv = xr[i];
        a0 = fmaf(xv, w[0][i], a0);
        a1 = fmaf(xv, w[1][i], a1);
        a2 = fmaf(xv, w[2][i], a2);
    }
    #pragma unroll
    for (int off = 16; off; off >>= 1) {
        a0 += __shfl_xor_sync(0xffffffffu, a0, off);
        a1 += __shfl_xor_sync(0xffffffffu, a1, off);
        a2 += __shfl_xor_sync(0xffffffffu, a2, off);
    }
    if (lane == 0) {
        out[row * 3 + 0] = 1.0f / (1.0f + expf(-(a0 + bb[0])));
        out[row * 3 + 1] = 1.0f / (1.0f + expf(-(a1 + bb[1])));
        out[row * 3 + 2] = 1.0f / (1.0f + expf(-(a2 + bb[2])));
    }
}

// ---------------- launch --------------------------------------------------------
extern "C" void kernel_launch(void* const* d_in, const int* in_sizes, int n_in,
                              void* d_out, int out_size)
{
    const float* points  = (const float*)d_in[0];
    const float* normals = (const float*)d_in[1];
    const float* fv      = (const float*)d_in[3];
    const float* pp      = (const float*)d_in[5];
    const float* rays    = (const float*)d_in[6];
    const float* ro      = (const float*)d_in[7];
    const float* W0 = (const float*)d_in[8];
    const float* b0 = (const float*)d_in[9];
    const float* W1 = (const float*)d_in[10];
    const float* b1 = (const float*)d_in[11];
    const float* W2 = (const float*)d_in[12];
    const float* b2 = (const float*)d_in[13];
    const float* W3 = (const float*)d_in[14];
    const float* b3 = (const float*)d_in[15];
    float* out = (float*)d_out;

    __nv_bfloat16 *xh, *xl, *h1h, *h1l, *h2h, *h2l;
    __nv_bfloat16 *w0h, *w0l, *w1h, *w1l, *w2h, *w2l;
    float *fin;
    cudaGetSymbolAddress((void**)&xh,  g_Xh);
    cudaGetSymbolAddress((void**)&xl,  g_Xl);
    cudaGetSymbolAddress((void**)&h1h, g_h1h);
    cudaGetSymbolAddress((void**)&h1l, g_h1l);
    cudaGetSymbolAddress((void**)&h2h, g_h2h);
    cudaGetSymbolAddress((void**)&h2l, g_h2l);
    cudaGetSymbolAddress((void**)&fin, g_fin);
    cudaGetSymbolAddress((void**)&w0h, g_w0h);
    cudaGetSymbolAddress((void**)&w0l, g_w0l);
    cudaGetSymbolAddress((void**)&w1h, g_w1h);
    cudaGetSymbolAddress((void**)&w1l, g_w1l);
    cudaGetSymbolAddress((void**)&w2h, g_w2h);
    cudaGetSymbolAddress((void**)&w2l, g_w2l);

    cudaFuncSetAttribute(feature_kernel,
                         cudaFuncAttributeMaxDynamicSharedMemorySize, FSMEM);
    cudaFuncSetAttribute(mma_gemm_kernel,
                         cudaFuncAttributeMaxDynamicSharedMemorySize, GSMEM);

    dim3 gg(NQ / BM, BN == 128 ? 2 : 1);

    feature_kernel<<<NQ / 128, 128, FSMEM>>>(points, normals, pp, rays, ro);  // 0
    copy_fv_kernel<<<(NQ * HD) / 256, 256>>>(fv);                             // 1
    convW_kernel<<<(HD * 512 + 255) / 256, 256>>>(W0, HD, D0, 512, w0h, w0l); // 2
    mma_gemm_kernel<<<gg, 256, GSMEM>>>(xh, xl, LDX, w0h, w0l, 512, b0,
                                        h1h, h1l, nullptr, 0);                // 3 <- ncu slot
    convW_kernel<<<(HD * HD + 255) / 256, 256>>>(W1, HD, HD, HD, w1h, w1l);   // 4
    mma_gemm_kernel<<<gg, 256, GSMEM>>>(h1h, h1l, HD, w1h, w1l, HD, b1,
                                        h2h, h2l, nullptr, 0);                // 5
    convW_kernel<<<(HD * HD + 255) / 256, 256>>>(W2, HD, HD, HD, w2h, w2l);   // 6
    mma_gemm_kernel<<<gg, 256, GSMEM>>>(h2h, h2l, HD, w2h, w2l, HD, b2,
                                        nullptr, nullptr, fin, 1);            // 7
    final_kernel<<<NQ / 8, 256>>>(fin, W3, b3, out);                          // 8
}

// round 5
// speedup vs baseline: 1.0151x; 1.0151x over previous
#include <cuda_runtime.h>
#include <cuda_bf16.h>
#include <math.h>
#include <cstdint>

#define NQ   24576        // R*S
#define SS   48
#define MP   4096
#define LDX  512          // padded feature stride (D0=511 + 1 zero col)
#define D0   511
#define HD   256

// ---------------- scratch (static device globals; no runtime alloc) ----------
// activations stored pre-split as bf16 hi/lo matrices
__device__ __nv_bfloat16 g_Xh[NQ * LDX], g_Xl[NQ * LDX];
__device__ __nv_bfloat16 g_h1h[NQ * HD], g_h1l[NQ * HD];
__device__ __nv_bfloat16 g_h2h[NQ * HD], g_h2l[NQ * HD];
__device__ float         g_fin[NQ * HD];
// pre-split weights (bf16 hi/lo), W0 padded K 511 -> 512
__device__ __nv_bfloat16 g_w0h[HD * 512], g_w0l[HD * 512];
__device__ __nv_bfloat16 g_w1h[HD * HD],  g_w1l[HD * HD];
__device__ __nv_bfloat16 g_w2h[HD * HD],  g_w2l[HD * HD];
// spatial grid
__device__ int    g_start[1001];
__device__ float4 g_sorted[MP];    // cell-ordered particles, .w = index bits

// ============================ helpers ========================================
__device__ __forceinline__ uint32_t smem_u32(const void* p) {
    uint32_t a;
    asm("{ .reg .u64 t; cvta.to.shared.u64 t, %1; cvt.u32.u64 %0, t; }"
        : "=r"(a) : "l"(p));
    return a;
}
__device__ __forceinline__ void ldm_x4(uint32_t* r, uint32_t addr) {
    asm volatile("ldmatrix.sync.aligned.m8n8.x4.shared.b16 {%0,%1,%2,%3}, [%4];"
        : "=r"(r[0]), "=r"(r[1]), "=r"(r[2]), "=r"(r[3]) : "r"(addr));
}
__device__ __forceinline__ void ldm_x2(uint32_t* r, uint32_t addr) {
    asm volatile("ldmatrix.sync.aligned.m8n8.x2.shared.b16 {%0,%1}, [%2];"
        : "=r"(r[0]), "=r"(r[1]) : "r"(addr));
}
__device__ __forceinline__ void mma_bf16(float* d, const uint32_t* a, const uint32_t* b) {
    asm volatile("mma.sync.aligned.m16n8k16.row.col.f32.bf16.bf16.f32 "
        "{%0,%1,%2,%3}, {%4,%5,%6,%7}, {%8,%9}, {%0,%1,%2,%3};"
        : "+f"(d[0]), "+f"(d[1]), "+f"(d[2]), "+f"(d[3])
        : "r"(a[0]), "r"(a[1]), "r"(a[2]), "r"(a[3]), "r"(b[0]), "r"(b[1]));
}
#define CP16(dst, src) \
    asm volatile("cp.async.cg.shared.global [%0], [%1], 16;" :: "r"(dst), "l"(src) : "memory")
#define CP_COMMIT() asm volatile("cp.async.commit_group;" ::: "memory")
#define CP_WAIT1()  asm volatile("cp.async.wait_group 1;" ::: "memory")

__device__ __forceinline__ uint32_t swz(uint32_t off) {
    return off ^ ((off >> 3) & 0x70);
}
__device__ __forceinline__ int cell_of(float x, float y, float z) {
    int cx = min(max(__float2int_rd(x * 10.0f), 0), 9);
    int cy = min(max(__float2int_rd(y * 10.0f), 0), 9);
    int cz = min(max(__float2int_rd(z * 10.0f), 0), 9);
    return cx + 10 * cy + 100 * cz;
}
// split-write: v -> bf16 hi + bf16 lo at idx
__device__ __forceinline__ void wsplit(__nv_bfloat16* H, __nv_bfloat16* L,
                                       size_t idx, float v) {
    __nv_bfloat16 h = __float2bfloat16(v);
    H[idx] = h;
    L[idx] = __float2bfloat16(v - __bfloat162float(h));
}
__device__ __forceinline__ void store2_split(__nv_bfloat16* H, __nv_bfloat16* L,
                                             size_t idx, float a, float b) {
    __nv_bfloat16 ha = __float2bfloat16(a), hb = __float2bfloat16(b);
    __nv_bfloat16 la = __float2bfloat16(a - __bfloat162float(ha));
    __nv_bfloat16 lb = __float2bfloat16(b - __bfloat162float(hb));
    uint32_t hw = (uint32_t)__bfloat16_as_ushort(ha) | ((uint32_t)__bfloat16_as_ushort(hb) << 16);
    uint32_t lw = (uint32_t)__bfloat16_as_ushort(la) | ((uint32_t)__bfloat16_as_ushort(lb) << 16);
    *(uint32_t*)(H + idx) = hw;
    *(uint32_t*)(L + idx) = lw;
}

// ---------------- grid build: ONE CTA does count + scan + scatter --------------
__global__ void __launch_bounds__(1024)
gridbuild_kernel(const float* __restrict__ pp)
{
    __shared__ int scnt[1000];
    __shared__ int ssc[1024];
    const int t = threadIdx.x;
    if (t < 1000) scnt[t] = 0;
    __syncthreads();
    for (int i = t; i < MP; i += 1024)
        atomicAdd(&scnt[cell_of(pp[3*i], pp[3*i+1], pp[3*i+2])], 1);
    __syncthreads();
    int v = (t < 1000) ? scnt[t] : 0;
    ssc[t] = v;
    __syncthreads();
    for (int d = 1; d < 1024; d <<= 1) {
        int u = (t >= d) ? ssc[t - d] : 0;
        __syncthreads();
        ssc[t] += u;
        __syncthreads();
    }
    if (t < 1000) { g_start[t] = ssc[t] - v; scnt[t] = ssc[t] - v; }
    if (t == 0)   g_start[1000] = MP;
    __syncthreads();
    for (int i = t; i < MP; i += 1024) {
        float x = pp[3*i], y = pp[3*i+1], z = pp[3*i+2];
        int c = cell_of(x, y, z);
        int pos = atomicAdd(&scnt[c], 1);
        g_sorted[pos] = make_float4(x, y, z, __int_as_float(i));
    }
}

// ---------------- posenc via double-angle recurrence ---------------------------
template<int C, int F>
__device__ __forceinline__ void posenc_write(__nv_bfloat16* H, __nv_bfloat16* L,
                                             int off, const float* v)
{
    float s[C], c[C];
    #pragma unroll
    for (int i = 0; i < C; i++) { wsplit(H, L, off + i, v[i]); sincosf(v[i], &s[i], &c[i]); }
    #pragma unroll
    for (int f = 0; f < F; f++) {
        #pragma unroll
        for (int i = 0; i < C; i++) {
            wsplit(H, L, off + C + f*2*C + i,     s[i]);
            wsplit(H, L, off + C + f*2*C + C + i, c[i]);
        }
        if (f + 1 < F) {
            #pragma unroll
            for (int i = 0; i < C; i++) {
                float ns = 2.0f * s[i] * c[i];
                float nc = fmaf(-2.0f * s[i], s[i], 1.0f);
                s[i] = ns; c[i] = nc;
            }
        }
    }
}

// ---------------- feature kernel: grid ball query + embeddings -----------------
#define FSMEM (MP * 16 + 1004 * 4)

__global__ void __launch_bounds__(128)
feature_kernel(const float* __restrict__ points,
               const float* __restrict__ normals,
               const float* __restrict__ rays,
               const float* __restrict__ ro)
{
    extern __shared__ char fsm[];
    float4* spts   = (float4*)fsm;
    int*    sstart = (int*)(fsm + MP * 16);

    const int tid = threadIdx.x;
    for (int i = tid; i < MP;   i += 128) spts[i]   = g_sorted[i];
    for (int i = tid; i < 1001; i += 128) sstart[i] = g_start[i];
    __syncthreads();

    const int gid = blockIdx.x * 128 + tid;
    const float qx = points[3*gid+0], qy = points[3*gid+1], qz = points[3*gid+2];

    const float R2  = (float)(0.1 * 0.1);   // fp64-computed threshold bits
    const float RAD = 0.1f;

    int cand[64];
    int cnt = 0;
    {
        int cx = min(max(__float2int_rd(qx * 10.0f), 0), 9);
        int cy = min(max(__float2int_rd(qy * 10.0f), 0), 9);
        int cz = min(max(__float2int_rd(qz * 10.0f), 0), 9);
        int x0 = max(cx-1,0), x1 = min(cx+1,9);
        int y0 = max(cy-1,0), y1 = min(cy+1,9);
        int z0 = max(cz-1,0), z1 = min(cz+1,9);
        for (int zz = z0; zz <= z1; zz++)
        for (int yy = y0; yy <= y1; yy++)
        for (int xx = x0; xx <= x1; xx++) {
            int c  = xx + 10*yy + 100*zz;
            int s0 = sstart[c], s1 = sstart[c+1];
            for (int i = s0; i < s1; i++) {
                float4 p = spts[i];
                float dx = p.x - qx, dy = p.y - qy, dz = p.z - qz;
                float d2 = dx*dx + dy*dy + dz*dz;
                if (d2 < R2 && cnt < 64)
                    cand[cnt++] = (__float_as_int(p.w) << 12) | i;
            }
        }
    }
    // sort ascending by original index -> first-k-by-index semantics
    for (int i = 1; i < cnt; i++) {
        int v = cand[i], j = i - 1;
        while (j >= 0 && cand[j] > v) { cand[j+1] = cand[j]; j--; }
        cand[j+1] = v;
    }
    const int kk = min(cnt, 16);
    float nx[16], ny[16], nz[16], nd[16];
    for (int k = 0; k < kk; k++) {
        float4 p = spts[cand[k] & 4095];
        float dx = p.x - qx, dy = p.y - qy, dz = p.z - qz;
        nx[k] = p.x; ny[k] = p.y; nz[k] = p.z;
        nd[k] = dx*dx + dy*dy + dz*dz;
    }

    float qn = sqrtf(qx*qx + qy*qy + qz*qz);
    float t0 = qn / RAD;
    float w0 = fmaxf(1.0f - t0*t0*t0, 0.0f);

    float density = 0.0f, smx = 0.0f, smy = 0.0f, smz = 0.0f;
    for (int k = 0; k < 16; k++) {
        if (k < kk) {
            float dn = sqrtf(nd[k]);
            float tt = dn / RAD;
            float w  = fmaxf(1.0f - tt*tt*tt, 0.0f);
            density += w;
            smx += w * nx[k]; smy += w * ny[k]; smz += w * nz[k];
        } else {
            density += w0;
        }
    }

    int   num_nn = 0;
    float sdx = 0.0f, sdy = 0.0f, sdz = 0.0f;
    for (int k = 0; k < kk; k++) {
        if (nd[k] != 0.0f) {
            num_nn++;
            sdx += nx[k] - qx; sdy += ny[k] - qy; sdz += nz[k] - qz;
        }
    }
    float inv = (float)num_nn + 1e-12f;
    float mx = sdx / inv, my = sdy / inv, mz = sdz / inv;
    float vx = 0.0f, vy = 0.0f, vz = 0.0f;
    for (int k = 0; k < kk; k++) {
        if (nd[k] != 0.0f) {
            float ex = (nx[k] - qx) - mx;
            float ey = (ny[k] - qy) - my;
            float ez = (nz[k] - qz) - mz;
            vx += ex*ex; vy += ey*ey; vz += ez*ez;
        }
    }
    vx /= inv; vy /= inv; vz /= inv;

    float dinv = density + 1e-12f;
    float spx = smx / dinv, spy = smy / dinv, spz = smz / dinv;
    float dirx = spx - ro[0], diry = spy - ro[1], dirz = spz - ro[2];
    float dl = sqrtf(dirx*dirx + diry*diry + dirz*dirz);
    dirx /= dl; diry /= dl; dirz /= dl;

    __nv_bfloat16* H = g_Xh + (size_t)gid * LDX;
    __nv_bfloat16* L = g_Xl + (size_t)gid * LDX;
    float q3[3]  = {qx, qy, qz};       posenc_write<3,10>(H, L, 0,   q3);
    float d1[1]  = {density};          posenc_write<1,4> (H, L, 63,  d1);
    float sp3[3] = {spx, spy, spz};    posenc_write<3,10>(H, L, 72,  sp3);
    float v3[3]  = {vx, vy, vz};       posenc_write<3,10>(H, L, 135, v3);
    int r = gid / SS;
    float rd[3]  = {rays[6*r+3], rays[6*r+4], rays[6*r+5]};
    posenc_write<3,4>(H, L, 198, rd);
    float dd[3]  = {dirx, diry, dirz}; posenc_write<3,4> (H, L, 225, dd);
    wsplit(H, L, 252, normals[3*gid+0]);
    wsplit(H, L, 253, normals[3*gid+1]);
    wsplit(H, L, 254, normals[3*gid+2]);
    H[511] = __float2bfloat16(0.0f);
    L[511] = __float2bfloat16(0.0f);
}

// ---------------- split-copy of feature_vectors into X[:,255:511] -------------
__global__ void __launch_bounds__(256)
copy_fv_kernel(const float* __restrict__ fv)
{
    int i = blockIdx.x * blockDim.x + threadIdx.x;
    if (i < NQ * HD) {
        int row = i >> 8;
        int col = i & 255;
        wsplit(g_Xh, g_Xl, (size_t)row * LDX + 255 + col, fv[i]);
    }
}

// ---------------- weight split: fp32 -> bf16 hi/lo, K padded to Kp -------------
__global__ void __launch_bounds__(256)
convW_kernel(const float* __restrict__ W, int N, int K, int Kp,
             __nv_bfloat16* __restrict__ Wh, __nv_bfloat16* __restrict__ Wl)
{
    int i = blockIdx.x * 256 + threadIdx.x;
    if (i >= N * Kp) return;
    int n = i / Kp, k = i - n * Kp;
    float v = (k < K) ? W[(size_t)n * K + k] : 0.0f;
    __nv_bfloat16 h = __float2bfloat16(v);
    float r = v - __bfloat162float(h);
    Wh[i] = h;
    Wl[i] = __float2bfloat16(r);
}

// ================= warp-mma split-bf16 GEMM: C = relu(A @ W^T + b) =============
// Block tile 128m x 128n x 32k, 8 warps (4m x 2n), cp.async 3-stage pipeline,
// ONE __syncthreads per K-tile, stage issued right after the barrier.
#define BM 128
#define BN 128
#define STAGE 32768            // A(hi|lo) 16KB + B(hi|lo) 16KB per stage
#define NSTAGE 3
#define GSMEM (NSTAGE * STAGE + 512)

__device__ __forceinline__ void stage_tile(
    uint32_t sb,
    const __nv_bfloat16* __restrict__ Ah, const __nv_bfloat16* __restrict__ Al, int lda,
    const __nv_bfloat16* __restrict__ Bh, const __nv_bfloat16* __restrict__ Bl, int ldb,
    int rowBase, int colBase, int k0, int tid)
{
    const int r = tid >> 2, c = tid & 3;
    #pragma unroll
    for (int i = 0; i < 2; i++) {
        int row = r + i * 64;
        size_t gi = (size_t)(rowBase + row) * lda + k0 + c * 8;
        uint32_t off = (uint32_t)(row << 7) + (uint32_t)(c << 4);
        CP16(sb + swz(off),      Ah + gi);
        CP16(sb + swz(off + 64), Al + gi);
    }
    #pragma unroll
    for (int i = 0; i < 2; i++) {
        int row = r + i * 64;
        size_t gi = (size_t)(colBase + row) * ldb + k0 + c * 8;
        uint32_t off = (uint32_t)(row << 7) + (uint32_t)(c << 4);
        CP16(sb + 16384 + swz(off),      Bh + gi);
        CP16(sb + 16384 + swz(off + 64), Bl + gi);
    }
}

__global__ void __launch_bounds__(256, 2)
mma_gemm_kernel(const __nv_bfloat16* __restrict__ Ah,
                const __nv_bfloat16* __restrict__ Al, int lda,
                const __nv_bfloat16* __restrict__ Bh,
                const __nv_bfloat16* __restrict__ Bl, int Kp,
                const float* __restrict__ bias,
                __nv_bfloat16* __restrict__ CH,
                __nv_bfloat16* __restrict__ CL,
                float* __restrict__ Cf,
                int outMode)
{
    extern __shared__ char gsm[];
    const uint32_t sbase = smem_u32(gsm);
    float* sbias = (float*)(gsm + NSTAGE * STAGE);

    const int tid  = threadIdx.x;
    const int wid  = tid >> 5;
    const int lane = tid & 31;
    const int wm   = wid & 3;          // 4 warps in m
    const int wn   = wid >> 2;         // 2 warps in n
    const int rowBase = blockIdx.x * BM;
    const int colBase = blockIdx.y * BN;

    if (tid < 128) sbias[tid] = bias[colBase + tid];

    float acc[2][8][4];
    #pragma unroll
    for (int mi = 0; mi < 2; mi++)
        #pragma unroll
        for (int ni = 0; ni < 8; ni++)
            #pragma unroll
            for (int e = 0; e < 4; e++) acc[mi][ni][e] = 0.0f;

    const int T = Kp / 32;

    // prologue: stage tiles 0,1 (groups #0, #1)
    stage_tile(sbase, Ah, Al, lda, Bh, Bl, Kp, rowBase, colBase, 0, tid);
    CP_COMMIT();
    stage_tile(sbase + STAGE, Ah, Al, lda, Bh, Bl, Kp, rowBase, colBase, 32, tid);
    CP_COMMIT();

    for (int t = 0; t < T; t++) {
        CP_WAIT1();          // tile t landed (<=1 pending group)
        __syncthreads();     // all warps done with compute(t-1) -> buffer (t+2)%3 free

        // stage tile t+2 immediately (2 tiles of compute to cover latency)
        if (t + 2 < T)
            stage_tile(sbase + (uint32_t)((t + 2) % NSTAGE) * STAGE,
                       Ah, Al, lda, Bh, Bl, Kp, rowBase, colBase, (t + 2) * 32, tid);
        CP_COMMIT();         // unconditional: keeps group arithmetic exact

        // ---- compute tile t ----
        const uint32_t aB = sbase + (uint32_t)(t % NSTAGE) * STAGE;
        const uint32_t bB = aB + 16384;
        #pragma unroll
        for (int ks = 0; ks < 2; ks++) {
            uint32_t bf[8][2][2];
            #pragma unroll
            for (int ni = 0; ni < 8; ni++)
                #pragma unroll
                for (int h = 0; h < 2; h++) {
                    int r  = wn * 64 + ni * 8 + (lane & 7);
                    int ch = h * 4 + ks * 2 + ((lane >> 3) & 1);
                    ldm_x2(bf[ni][h], bB + swz((uint32_t)(r << 7) + (uint32_t)(ch << 4)));
                }
            #pragma unroll
            for (int mi = 0; mi < 2; mi++) {
                uint32_t afh[4], afl[4];
                {
                    int r  = wm * 32 + mi * 16 + (lane & 15);
                    int c0 = ks * 2 + (lane >> 4);
                    ldm_x4(afh, aB + swz((uint32_t)(r << 7) + (uint32_t)(c0 << 4)));
                    ldm_x4(afl, aB + swz((uint32_t)(r << 7) + (uint32_t)((c0 + 4) << 4)));
                }
                #pragma unroll
                for (int ni = 0; ni < 8; ni++) {
                    mma_bf16(acc[mi][ni], afh, bf[ni][0]);  // Ah*Bh
                    mma_bf16(acc[mi][ni], afh, bf[ni][1]);  // Ah*Bl
                    mma_bf16(acc[mi][ni], afl, bf[ni][0]);  // Al*Bh
                }
            }
        }
    }

    // ---- epilogue: bias + relu + store (split bf16 or fp32) ----
    #pragma unroll
    for (int mi = 0; mi < 2; mi++)
        #pragma unroll
        for (int ni = 0; ni < 8; ni++) {
            int m  = rowBase + wm * 32 + mi * 16 + (lane >> 2);
            int nl = wn * 64 + ni * 8 + ((lane & 3) << 1);
            int n  = colBase + nl;
            float b0 = sbias[nl], b1 = sbias[nl + 1];
            float v00 = fmaxf(acc[mi][ni][0] + b0, 0.0f);
            float v01 = fmaxf(acc[mi][ni][1] + b1, 0.0f);
            float v10 = fmaxf(acc[mi][ni][2] + b0, 0.0f);
            float v11 = fmaxf(acc[mi][ni][3] + b1, 0.0f);
            if (outMode == 0) {
                store2_split(CH, CL, (size_t)m * HD + n,       v00, v01);
                store2_split(CH, CL, (size_t)(m + 8) * HD + n, v10, v11);
            } else {
                *(float2*)(Cf + (size_t)m * HD + n)       = make_float2(v00, v01);
                *(float2*)(Cf + (size_t)(m + 8) * HD + n) = make_float2(v10, v11);
            }
        }
}

// ---------------- final layer: out = sigmoid(X @ W3^T + b3), W3 [3,256] --------
__global__ void __launch_bounds__(256)
final_kernel(const float* __restrict__ Xin,
             const float* __restrict__ W3,
             const float* __restrict__ b3,
             float* __restrict__ out)
{
    __shared__ float w[3][256];
    __shared__ float bb[3];
    const int tid = threadIdx.x;
    for (int i = tid; i < 768; i += 256) w[i >> 8][i & 255] = W3[i];
    if (tid < 3) bb[tid] = b3[tid];
    __syncthreads();

    const int warp = tid >> 5, lane = tid & 31;
    const int row = blockIdx.x * 8 + warp;
    const float* xr = Xin + (size_t)row * HD;

    float a0 = 0.0f, a1 = 0.0f, a2 = 0.0f;
    #pragma unroll
    for (int i = lane; i < HD; i += 32) {
        float xv = xr[i];
        a0 = fmaf(xv, w[0][i], a0);
        a1 = fmaf(xv, w[1][i], a1);
        a2 = fmaf(xv, w[2][i], a2);
    }
    #pragma unroll
    for (int off = 16; off; off >>= 1) {
        a0 += __shfl_xor_sync(0xffffffffu, a0, off);
        a1 += __shfl_xor_sync(0xffffffffu, a1, off);
        a2 += __shfl_xor_sync(0xffffffffu, a2, off);
    }
    if (lane == 0) {
        out[row * 3 + 0] = 1.0f / (1.0f + expf(-(a0 + bb[0])));
        out[row * 3 + 1] = 1.0f / (1.0f + expf(-(a1 + bb[1])));
        out[row * 3 + 2] = 1.0f / (1.0f + expf(-(a2 + bb[2])));
    }
}

// ---------------- launch --------------------------------------------------------
extern "C" void kernel_launch(void* const* d_in, const int* in_sizes, int n_in,
                              void* d_out, int out_size)
{
    const float* points  = (const float*)d_in[0];
    const float* normals = (const float*)d_in[1];
    const float* fv      = (const float*)d_in[3];
    const float* pp      = (const float*)d_in[5];
    const float* rays    = (const float*)d_in[6];
    const float* ro      = (const float*)d_in[7];
    const float* W0 = (const float*)d_in[8];
    const float* b0 = (const float*)d_in[9];
    const float* W1 = (const float*)d_in[10];
    const float* b1 = (const float*)d_in[11];
    const float* W2 = (const float*)d_in[12];
    const float* b2 = (const float*)d_in[13];
    const float* W3 = (const float*)d_in[14];
    const float* b3 = (const float*)d_in[15];
    float* out = (float*)d_out;

    __nv_bfloat16 *xh, *xl, *h1h, *h1l, *h2h, *h2l;
    __nv_bfloat16 *w0h, *w0l, *w1h, *w1l, *w2h, *w2l;
    float *fin;
    cudaGetSymbolAddress((void**)&xh,  g_Xh);
    cudaGetSymbolAddress((void**)&xl,  g_Xl);
    cudaGetSymbolAddress((void**)&h1h, g_h1h);
    cudaGetSymbolAddress((void**)&h1l, g_h1l);
    cudaGetSymbolAddress((void**)&h2h, g_h2h);
    cudaGetSymbolAddress((void**)&h2l, g_h2l);
    cudaGetSymbolAddress((void**)&fin, g_fin);
    cudaGetSymbolAddress((void**)&w0h, g_w0h);
    cudaGetSymbolAddress((void**)&w0l, g_w0l);
    cudaGetSymbolAddress((void**)&w1h, g_w1h);
    cudaGetSymbolAddress((void**)&w1l, g_w1l);
    cudaGetSymbolAddress((void**)&w2h, g_w2h);
    cudaGetSymbolAddress((void**)&w2l, g_w2l);

    cudaFuncSetAttribute(feature_kernel,
                         cudaFuncAttributeMaxDynamicSharedMemorySize, FSMEM);
    cudaFuncSetAttribute(mma_gemm_kernel,
                         cudaFuncAttributeMaxDynamicSharedMemorySize, GSMEM);

    dim3 gg(NQ / BM, 2);

    gridbuild_kernel<<<1, 1024>>>(pp);                                        // 0
    feature_kernel<<<NQ / 128, 128, FSMEM>>>(points, normals, rays, ro);      // 1
    copy_fv_kernel<<<(NQ * HD) / 256, 256>>>(fv);                             // 2
    convW_kernel<<<(HD * 512 + 255) / 256, 256>>>(W0, HD, D0, 512, w0h, w0l); // 3
    convW_kernel<<<(HD * HD + 255) / 256, 256>>>(W1, HD, HD, HD, w1h, w1l);   // 4
    mma_gemm_kernel<<<gg, 256, GSMEM>>>(xh, xl, LDX, w0h, w0l, 512, b0,
                                        h1h, h1l, nullptr, 0);                // 5 <- ncu slot
    mma_gemm_kernel<<<gg, 256, GSMEM>>>(h1h, h1l, HD, w1h, w1l, HD, b1,
                                        h2h, h2l, nullptr, 0);                // 6
    convW_kernel<<<(HD * HD + 255) / 256, 256>>>(W2, HD, HD, HD, w2h, w2l);   // 7
    mma_gemm_kernel<<<gg, 256, GSMEM>>>(h2h, h2l, HD, w2h, w2l, HD, b2,
                                        nullptr, nullptr, fin, 1);            // 8
    final_kernel<<<NQ / 8, 256>>>(fin, W3, b3, out);                          // 9
}

// round 6
// speedup vs baseline: 1.0299x; 1.0145x over previous
#include <cuda_runtime.h>
#include <cuda_bf16.h>
#include <math.h>
#include <cstdint>

#define NQ   24576        // R*S
#define SS   48
#define MP   4096
#define LDX  512          // padded feature stride (D0=511 + 1 zero col)
#define D0   511
#define HD   256

// ---------------- scratch (static device globals; no runtime alloc) ----------
// activations stored pre-split as bf16 hi/lo matrices
__device__ __nv_bfloat16 g_Xh[NQ * LDX], g_Xl[NQ * LDX];
__device__ __nv_bfloat16 g_h1h[NQ * HD], g_h1l[NQ * HD];
__device__ __nv_bfloat16 g_h2h[NQ * HD], g_h2l[NQ * HD];
__device__ float         g_fin[NQ * HD];
// pre-split weights (bf16 hi/lo), W0 padded K 511 -> 512
__device__ __nv_bfloat16 g_w0h[HD * 512], g_w0l[HD * 512];
__device__ __nv_bfloat16 g_w1h[HD * HD],  g_w1l[HD * HD];
__device__ __nv_bfloat16 g_w2h[HD * HD],  g_w2l[HD * HD];
// spatial grid
__device__ int    g_start[1001];
__device__ float4 g_sorted[MP];    // cell-ordered particles, .w = index bits

// ============================ helpers ========================================
__device__ __forceinline__ uint32_t smem_u32(const void* p) {
    uint32_t a;
    asm("{ .reg .u64 t; cvta.to.shared.u64 t, %1; cvt.u32.u64 %0, t; }"
        : "=r"(a) : "l"(p));
    return a;
}
__device__ __forceinline__ void ldm_x4(uint32_t* r, uint32_t addr) {
    asm volatile("ldmatrix.sync.aligned.m8n8.x4.shared.b16 {%0,%1,%2,%3}, [%4];"
        : "=r"(r[0]), "=r"(r[1]), "=r"(r[2]), "=r"(r[3]) : "r"(addr));
}
__device__ __forceinline__ void mma_bf16(float* d, const uint32_t* a, const uint32_t* b) {
    asm volatile("mma.sync.aligned.m16n8k16.row.col.f32.bf16.bf16.f32 "
        "{%0,%1,%2,%3}, {%4,%5,%6,%7}, {%8,%9}, {%0,%1,%2,%3};"
        : "+f"(d[0]), "+f"(d[1]), "+f"(d[2]), "+f"(d[3])
        : "r"(a[0]), "r"(a[1]), "r"(a[2]), "r"(a[3]), "r"(b[0]), "r"(b[1]));
}
#define CP16(dst, src) \
    asm volatile("cp.async.cg.shared.global [%0], [%1], 16;" :: "r"(dst), "l"(src) : "memory")
#define CP_COMMIT() asm volatile("cp.async.commit_group;" ::: "memory")
#define CP_WAIT2()  asm volatile("cp.async.wait_group 2;" ::: "memory")

__device__ __forceinline__ uint32_t swz(uint32_t off) {
    return off ^ ((off >> 3) & 0x70);
}
__device__ __forceinline__ int cell_of(float x, float y, float z) {
    int cx = min(max(__float2int_rd(x * 10.0f), 0), 9);
    int cy = min(max(__float2int_rd(y * 10.0f), 0), 9);
    int cz = min(max(__float2int_rd(z * 10.0f), 0), 9);
    return cx + 10 * cy + 100 * cz;
}
// split-write: v -> bf16 hi + bf16 lo at idx
__device__ __forceinline__ void wsplit(__nv_bfloat16* H, __nv_bfloat16* L,
                                       size_t idx, float v) {
    __nv_bfloat16 h = __float2bfloat16(v);
    H[idx] = h;
    L[idx] = __float2bfloat16(v - __bfloat162float(h));
}
__device__ __forceinline__ void store2_split(__nv_bfloat16* H, __nv_bfloat16* L,
                                             size_t idx, float a, float b) {
    __nv_bfloat16 ha = __float2bfloat16(a), hb = __float2bfloat16(b);
    __nv_bfloat16 la = __float2bfloat16(a - __bfloat162float(ha));
    __nv_bfloat16 lb = __float2bfloat16(b - __bfloat162float(hb));
    uint32_t hw = (uint32_t)__bfloat16_as_ushort(ha) | ((uint32_t)__bfloat16_as_ushort(hb) << 16);
    uint32_t lw = (uint32_t)__bfloat16_as_ushort(la) | ((uint32_t)__bfloat16_as_ushort(lb) << 16);
    *(uint32_t*)(H + idx) = hw;
    *(uint32_t*)(L + idx) = lw;
}

// ---------------- grid build: ONE CTA does count + scan + scatter --------------
__global__ void __launch_bounds__(1024)
gridbuild_kernel(const float* __restrict__ pp)
{
    __shared__ int scnt[1000];
    __shared__ int ssc[1024];
    const int t = threadIdx.x;
    if (t < 1000) scnt[t] = 0;
    __syncthreads();
    for (int i = t; i < MP; i += 1024)
        atomicAdd(&scnt[cell_of(pp[3*i], pp[3*i+1], pp[3*i+2])], 1);
    __syncthreads();
    int v = (t < 1000) ? scnt[t] : 0;
    ssc[t] = v;
    __syncthreads();
    for (int d = 1; d < 1024; d <<= 1) {
        int u = (t >= d) ? ssc[t - d] : 0;
        __syncthreads();
        ssc[t] += u;
        __syncthreads();
    }
    if (t < 1000) { g_start[t] = ssc[t] - v; scnt[t] = ssc[t] - v; }
    if (t == 0)   g_start[1000] = MP;
    __syncthreads();
    for (int i = t; i < MP; i += 1024) {
        float x = pp[3*i], y = pp[3*i+1], z = pp[3*i+2];
        int c = cell_of(x, y, z);
        int pos = atomicAdd(&scnt[c], 1);
        g_sorted[pos] = make_float4(x, y, z, __int_as_float(i));
    }
}

// ---------------- posenc via double-angle recurrence ---------------------------
template<int C, int F>
__device__ __forceinline__ void posenc_write(__nv_bfloat16* H, __nv_bfloat16* L,
                                             int off, const float* v)
{
    float s[C], c[C];
    #pragma unroll
    for (int i = 0; i < C; i++) { wsplit(H, L, off + i, v[i]); sincosf(v[i], &s[i], &c[i]); }
    #pragma unroll
    for (int f = 0; f < F; f++) {
        #pragma unroll
        for (int i = 0; i < C; i++) {
            wsplit(H, L, off + C + f*2*C + i,     s[i]);
            wsplit(H, L, off + C + f*2*C + C + i, c[i]);
        }
        if (f + 1 < F) {
            #pragma unroll
            for (int i = 0; i < C; i++) {
                float ns = 2.0f * s[i] * c[i];
                float nc = fmaf(-2.0f * s[i], s[i], 1.0f);
                s[i] = ns; c[i] = nc;
            }
        }
    }
}

// ---------------- feature kernel: grid ball query + embeddings -----------------
#define FSMEM (MP * 16 + 1004 * 4)

__global__ void __launch_bounds__(128)
feature_kernel(const float* __restrict__ points,
               const float* __restrict__ normals,
               const float* __restrict__ rays,
               const float* __restrict__ ro)
{
    extern __shared__ char fsm[];
    float4* spts   = (float4*)fsm;
    int*    sstart = (int*)(fsm + MP * 16);

    const int tid = threadIdx.x;
    for (int i = tid; i < MP;   i += 128) spts[i]   = g_sorted[i];
    for (int i = tid; i < 1001; i += 128) sstart[i] = g_start[i];
    __syncthreads();

    const int gid = blockIdx.x * 128 + tid;
    const float qx = points[3*gid+0], qy = points[3*gid+1], qz = points[3*gid+2];

    const float R2  = (float)(0.1 * 0.1);   // fp64-computed threshold bits
    const float RAD = 0.1f;

    int cand[64];
    int cnt = 0;
    {
        int cx = min(max(__float2int_rd(qx * 10.0f), 0), 9);
        int cy = min(max(__float2int_rd(qy * 10.0f), 0), 9);
        int cz = min(max(__float2int_rd(qz * 10.0f), 0), 9);
        int x0 = max(cx-1,0), x1 = min(cx+1,9);
        int y0 = max(cy-1,0), y1 = min(cy+1,9);
        int z0 = max(cz-1,0), z1 = min(cz+1,9);
        for (int zz = z0; zz <= z1; zz++)
        for (int yy = y0; yy <= y1; yy++)
        for (int xx = x0; xx <= x1; xx++) {
            int c  = xx + 10*yy + 100*zz;
            int s0 = sstart[c], s1 = sstart[c+1];
            for (int i = s0; i < s1; i++) {
                float4 p = spts[i];
                float dx = p.x - qx, dy = p.y - qy, dz = p.z - qz;
                float d2 = dx*dx + dy*dy + dz*dz;
                if (d2 < R2 && cnt < 64)
                    cand[cnt++] = (__float_as_int(p.w) << 12) | i;
            }
        }
    }
    // sort ascending by original index -> first-k-by-index semantics
    for (int i = 1; i < cnt; i++) {
        int v = cand[i], j = i - 1;
        while (j >= 0 && cand[j] > v) { cand[j+1] = cand[j]; j--; }
        cand[j+1] = v;
    }
    const int kk = min(cnt, 16);
    float nx[16], ny[16], nz[16], nd[16];
    for (int k = 0; k < kk; k++) {
        float4 p = spts[cand[k] & 4095];
        float dx = p.x - qx, dy = p.y - qy, dz = p.z - qz;
        nx[k] = p.x; ny[k] = p.y; nz[k] = p.z;
        nd[k] = dx*dx + dy*dy + dz*dz;
    }

    float qn = sqrtf(qx*qx + qy*qy + qz*qz);
    float t0 = qn / RAD;
    float w0 = fmaxf(1.0f - t0*t0*t0, 0.0f);

    float density = 0.0f, smx = 0.0f, smy = 0.0f, smz = 0.0f;
    for (int k = 0; k < 16; k++) {
        if (k < kk) {
            float dn = sqrtf(nd[k]);
            float tt = dn / RAD;
            float w  = fmaxf(1.0f - tt*tt*tt, 0.0f);
            density += w;
            smx += w * nx[k]; smy += w * ny[k]; smz += w * nz[k];
        } else {
            density += w0;
        }
    }

    int   num_nn = 0;
    float sdx = 0.0f, sdy = 0.0f, sdz = 0.0f;
    for (int k = 0; k < kk; k++) {
        if (nd[k] != 0.0f) {
            num_nn++;
            sdx += nx[k] - qx; sdy += ny[k] - qy; sdz += nz[k] - qz;
        }
    }
    float inv = (float)num_nn + 1e-12f;
    float mx = sdx / inv, my = sdy / inv, mz = sdz / inv;
    float vx = 0.0f, vy = 0.0f, vz = 0.0f;
    for (int k = 0; k < kk; k++) {
        if (nd[k] != 0.0f) {
            float ex = (nx[k] - qx) - mx;
            float ey = (ny[k] - qy) - my;
            float ez = (nz[k] - qz) - mz;
            vx += ex*ex; vy += ey*ey; vz += ez*ez;
        }
    }
    vx /= inv; vy /= inv; vz /= inv;

    float dinv = density + 1e-12f;
    float spx = smx / dinv, spy = smy / dinv, spz = smz / dinv;
    float dirx = spx - ro[0], diry = spy - ro[1], dirz = spz - ro[2];
    float dl = sqrtf(dirx*dirx + diry*diry + dirz*dirz);
    dirx /= dl; diry /= dl; dirz /= dl;

    __nv_bfloat16* H = g_Xh + (size_t)gid * LDX;
    __nv_bfloat16* L = g_Xl + (size_t)gid * LDX;
    float q3[3]  = {qx, qy, qz};       posenc_write<3,10>(H, L, 0,   q3);
    float d1[1]  = {density};          posenc_write<1,4> (H, L, 63,  d1);
    float sp3[3] = {spx, spy, spz};    posenc_write<3,10>(H, L, 72,  sp3);
    float v3[3]  = {vx, vy, vz};       posenc_write<3,10>(H, L, 135, v3);
    int r = gid / SS;
    float rd[3]  = {rays[6*r+3], rays[6*r+4], rays[6*r+5]};
    posenc_write<3,4>(H, L, 198, rd);
    float dd[3]  = {dirx, diry, dirz}; posenc_write<3,4> (H, L, 225, dd);
    wsplit(H, L, 252, normals[3*gid+0]);
    wsplit(H, L, 253, normals[3*gid+1]);
    wsplit(H, L, 254, normals[3*gid+2]);
    H[511] = __float2bfloat16(0.0f);
    L[511] = __float2bfloat16(0.0f);
}

// ---------------- split-copy of feature_vectors into X[:,255:511] -------------
__global__ void __launch_bounds__(256)
copy_fv_kernel(const float* __restrict__ fv)
{
    int i = blockIdx.x * blockDim.x + threadIdx.x;
    if (i < NQ * HD) {
        int row = i >> 8;
        int col = i & 255;
        wsplit(g_Xh, g_Xl, (size_t)row * LDX + 255 + col, fv[i]);
    }
}

// ---------------- weight split: fp32 -> bf16 hi/lo, K padded to Kp -------------
__global__ void __launch_bounds__(256)
convW_kernel(const float* __restrict__ W, int N, int K, int Kp,
             __nv_bfloat16* __restrict__ Wh, __nv_bfloat16* __restrict__ Wl)
{
    int i = blockIdx.x * 256 + threadIdx.x;
    if (i >= N * Kp) return;
    int n = i / Kp, k = i - n * Kp;
    float v = (k < K) ? W[(size_t)n * K + k] : 0.0f;
    __nv_bfloat16 h = __float2bfloat16(v);
    float r = v - __bfloat162float(h);
    Wh[i] = h;
    Wl[i] = __float2bfloat16(r);
}

// ================= warp-mma split-bf16 GEMM: C = relu(A @ W^T + b) =============
// Block tile 128m x 64n x 32k, 8 warps (4m x 2n), warp tile 32m x 32n,
// cp.async 4-stage pipeline, all fragments for the tile loaded up-front,
// B fragments packed ldm_x4 (both hi/lo halves per instruction).
#define BM 128
#define BN 64
#define ASZ 16384                  // A hi|lo: 128 rows x 128B
#define BSZ 8192                   // B hi|lo: 64 rows x 128B
#define STAGE (ASZ + BSZ)          // 24 KB
#define NSTAGE 4
#define GSMEM (NSTAGE * STAGE + 512)

__device__ __forceinline__ void stage_tile(
    uint32_t sb,
    const __nv_bfloat16* __restrict__ Ah, const __nv_bfloat16* __restrict__ Al, int lda,
    const __nv_bfloat16* __restrict__ Bh, const __nv_bfloat16* __restrict__ Bl, int ldb,
    int rowBase, int colBase, int k0, int tid)
{
    // A: 1024 16B-units (row = u>>3, colunit = u&7; units 0-3 hi, 4-7 lo)
    #pragma unroll
    for (int i = 0; i < 4; i++) {
        int u = tid + i * 256;
        int r = u >> 3, cu = u & 7;
        const __nv_bfloat16* src = (cu < 4)
            ? Ah + (size_t)(rowBase + r) * lda + k0 + cu * 8
            : Al + (size_t)(rowBase + r) * lda + k0 + (cu - 4) * 8;
        CP16(sb + swz((uint32_t)(r << 7) + (uint32_t)(cu << 4)), src);
    }
    // B: 512 16B-units
    #pragma unroll
    for (int i = 0; i < 2; i++) {
        int u = tid + i * 256;
        int r = u >> 3, cu = u & 7;
        const __nv_bfloat16* src = (cu < 4)
            ? Bh + (size_t)(colBase + r) * ldb + k0 + cu * 8
            : Bl + (size_t)(colBase + r) * ldb + k0 + (cu - 4) * 8;
        CP16(sb + ASZ + swz((uint32_t)(r << 7) + (uint32_t)(cu << 4)), src);
    }
}

__global__ void __launch_bounds__(256, 2)
mma_gemm_kernel(const __nv_bfloat16* __restrict__ Ah,
                const __nv_bfloat16* __restrict__ Al, int lda,
                const __nv_bfloat16* __restrict__ Bh,
                const __nv_bfloat16* __restrict__ Bl, int Kp,
                const float* __restrict__ bias,
                __nv_bfloat16* __restrict__ CH,
                __nv_bfloat16* __restrict__ CL,
                float* __restrict__ Cf,
                int outMode)
{
    extern __shared__ char gsm[];
    const uint32_t sbase = smem_u32(gsm);
    float* sbias = (float*)(gsm + NSTAGE * STAGE);

    const int tid  = threadIdx.x;
    const int wid  = tid >> 5;
    const int lane = tid & 31;
    const int wm   = wid & 3;          // 4 warps in m
    const int wn   = wid >> 2;         // 2 warps in n
    const int rowBase = blockIdx.x * BM;
    const int colBase = blockIdx.y * BN;

    if (tid < BN) sbias[tid] = bias[colBase + tid];

    float acc[2][4][4];
    #pragma unroll
    for (int mi = 0; mi < 2; mi++)
        #pragma unroll
        for (int ni = 0; ni < 4; ni++)
            #pragma unroll
            for (int e = 0; e < 4; e++) acc[mi][ni][e] = 0.0f;

    const int T = Kp / 32;

    // prologue: stage tiles 0,1,2
    stage_tile(sbase,             Ah, Al, lda, Bh, Bl, Kp, rowBase, colBase, 0,  tid);
    CP_COMMIT();
    stage_tile(sbase + STAGE,     Ah, Al, lda, Bh, Bl, Kp, rowBase, colBase, 32, tid);
    CP_COMMIT();
    stage_tile(sbase + 2 * STAGE, Ah, Al, lda, Bh, Bl, Kp, rowBase, colBase, 64, tid);
    CP_COMMIT();

    // ldmatrix address precompute (per-lane constants)
    const uint32_t aRow = (uint32_t)(wm * 32 + (lane & 15));
    const uint32_t aC0  = (uint32_t)(lane >> 4);
    const uint32_t bRow = (uint32_t)(wn * 32 + (lane & 7));
    const uint32_t bCh  = (uint32_t)(((lane >> 4) & 1) * 4 + ((lane >> 3) & 1));

    for (int t = 0; t < T; t++) {
        CP_WAIT2();          // tile t landed
        __syncthreads();     // buffer (t+3)%4 free (consumed by compute t-1)

        if (t + 3 < T)
            stage_tile(sbase + (uint32_t)((t + 3) % NSTAGE) * STAGE,
                       Ah, Al, lda, Bh, Bl, Kp, rowBase, colBase, (t + 3) * 32, tid);
        CP_COMMIT();         // unconditional: keeps group arithmetic exact

        const uint32_t aB = sbase + (uint32_t)(t % NSTAGE) * STAGE;
        const uint32_t bB = aB + ASZ;

        // ---- load ALL fragments for this tile (16 LDSM) ----
        uint32_t af[2][2][2][4];   // [ks][mi][h][4]
        uint32_t bf[2][4][4];      // [ks][ni][4] (regs 0-1 = Bhi frag, 2-3 = Blo frag)
        #pragma unroll
        for (int ks = 0; ks < 2; ks++) {
            #pragma unroll
            for (int mi = 0; mi < 2; mi++) {
                uint32_t r  = aRow + mi * 16;
                uint32_t c0 = (uint32_t)(ks * 2) + aC0;
                ldm_x4(af[ks][mi][0], aB + swz((r << 7) + (c0 << 4)));
                ldm_x4(af[ks][mi][1], aB + swz((r << 7) + ((c0 + 4) << 4)));
            }
            #pragma unroll
            for (int ni = 0; ni < 4; ni++) {
                uint32_t r  = bRow + ni * 8;
                uint32_t ch = bCh + (uint32_t)(ks * 2);
                ldm_x4(bf[ks][ni], bB + swz((r << 7) + (ch << 4)));
            }
        }
        // ---- 48 MMAs, back-to-back ----
        #pragma unroll
        for (int ks = 0; ks < 2; ks++)
            #pragma unroll
            for (int mi = 0; mi < 2; mi++)
                #pragma unroll
                for (int ni = 0; ni < 4; ni++) {
                    mma_bf16(acc[mi][ni], af[ks][mi][0], &bf[ks][ni][0]);  // Ah*Bh
                    mma_bf16(acc[mi][ni], af[ks][mi][0], &bf[ks][ni][2]);  // Ah*Bl
                    mma_bf16(acc[mi][ni], af[ks][mi][1], &bf[ks][ni][0]);  // Al*Bh
                }
    }

    // ---- epilogue: bias + relu + store (split bf16 or fp32) ----
    #pragma unroll
    for (int mi = 0; mi < 2; mi++)
        #pragma unroll
        for (int ni = 0; ni < 4; ni++) {
            int m  = rowBase + wm * 32 + mi * 16 + (lane >> 2);
            int nl = wn * 32 + ni * 8 + ((lane & 3) << 1);
            int n  = colBase + nl;
            float b0 = sbias[nl], b1 = sbias[nl + 1];
            float v00 = fmaxf(acc[mi][ni][0] + b0, 0.0f);
            float v01 = fmaxf(acc[mi][ni][1] + b1, 0.0f);
            float v10 = fmaxf(acc[mi][ni][2] + b0, 0.0f);
            float v11 = fmaxf(acc[mi][ni][3] + b1, 0.0f);
            if (outMode == 0) {
                store2_split(CH, CL, (size_t)m * HD + n,       v00, v01);
                store2_split(CH, CL, (size_t)(m + 8) * HD + n, v10, v11);
            } else {
                *(float2*)(Cf + (size_t)m * HD + n)       = make_float2(v00, v01);
                *(float2*)(Cf + (size_t)(m + 8) * HD + n) = make_float2(v10, v11);
            }
        }
}

// ---------------- final layer: out = sigmoid(X @ W3^T + b3), W3 [3,256] --------
__global__ void __launch_bounds__(256)
final_kernel(const float* __restrict__ Xin,
             const float* __restrict__ W3,
             const float* __restrict__ b3,
             float* __restrict__ out)
{
    __shared__ float w[3][256];
    __shared__ float bb[3];
    const int tid = threadIdx.x;
    for (int i = tid; i < 768; i += 256) w[i >> 8][i & 255] = W3[i];
    if (tid < 3) bb[tid] = b3[tid];
    __syncthreads();

    const int warp = tid >> 5, lane = tid & 31;
    const int row = blockIdx.x * 8 + warp;
    const float* xr = Xin + (size_t)row * HD;

    float a0 = 0.0f, a1 = 0.0f, a2 = 0.0f;
    #pragma unroll
    for (int i = lane; i < HD; i += 32) {
        float xv = xr[i];
        a0 = fmaf(xv, w[0][i], a0);
        a1 = fmaf(xv, w[1][i], a1);
        a2 = fmaf(xv, w[2][i], a2);
    }
    #pragma unroll
    for (int off = 16; off; off >>= 1) {
        a0 += __shfl_xor_sync(0xffffffffu, a0, off);
        a1 += __shfl_xor_sync(0xffffffffu, a1, off);
        a2 += __shfl_xor_sync(0xffffffffu, a2, off);
    }
    if (lane == 0) {
        out[row * 3 + 0] = 1.0f / (1.0f + expf(-(a0 + bb[0])));
        out[row * 3 + 1] = 1.0f / (1.0f + expf(-(a1 + bb[1])));
        out[row * 3 + 2] = 1.0f / (1.0f + expf(-(a2 + bb[2])));
    }
}

// ---------------- launch --------------------------------------------------------
extern "C" void kernel_launch(void* const* d_in, const int* in_sizes, int n_in,
                              void* d_out, int out_size)
{
    const float* points  = (const float*)d_in[0];
    const float* normals = (const float*)d_in[1];
    const float* fv      = (const float*)d_in[3];
    const float* pp      = (const float*)d_in[5];
    const float* rays    = (const float*)d_in[6];
    const float* ro      = (const float*)d_in[7];
    const float* W0 = (const float*)d_in[8];
    const float* b0 = (const float*)d_in[9];
    const float* W1 = (const float*)d_in[10];
    const float* b1 = (const float*)d_in[11];
    const float* W2 = (const float*)d_in[12];
    const float* b2 = (const float*)d_in[13];
    const float* W3 = (const float*)d_in[14];
    const float* b3 = (const float*)d_in[15];
    float* out = (float*)d_out;

    __nv_bfloat16 *xh, *xl, *h1h, *h1l, *h2h, *h2l;
    __nv_bfloat16 *w0h, *w0l, *w1h, *w1l, *w2h, *w2l;
    float *fin;
    cudaGetSymbolAddress((void**)&xh,  g_Xh);
    cudaGetSymbolAddress((void**)&xl,  g_Xl);
    cudaGetSymbolAddress((void**)&h1h, g_h1h);
    cudaGetSymbolAddress((void**)&h1l, g_h1l);
    cudaGetSymbolAddress((void**)&h2h, g_h2h);
    cudaGetSymbolAddress((void**)&h2l, g_h2l);
    cudaGetSymbolAddress((void**)&fin, g_fin);
    cudaGetSymbolAddress((void**)&w0h, g_w0h);
    cudaGetSymbolAddress((void**)&w0l, g_w0l);
    cudaGetSymbolAddress((void**)&w1h, g_w1h);
    cudaGetSymbolAddress((void**)&w1l, g_w1l);
    cudaGetSymbolAddress((void**)&w2h, g_w2h);
    cudaGetSymbolAddress((void**)&w2l, g_w2l);

    cudaFuncSetAttribute(feature_kernel,
                         cudaFuncAttributeMaxDynamicSharedMemorySize, FSMEM);
    cudaFuncSetAttribute(mma_gemm_kernel,
                         cudaFuncAttributeMaxDynamicSharedMemorySize, GSMEM);

    dim3 gg(NQ / BM, HD / BN);   // 192 x 4 = 768 CTAs

    gridbuild_kernel<<<1, 1024>>>(pp);                                        // 0
    feature_kernel<<<NQ / 128, 128, FSMEM>>>(points, normals, rays, ro);      // 1
    copy_fv_kernel<<<(NQ * HD) / 256, 256>>>(fv);                             // 2
    convW_kernel<<<(HD * 512 + 255) / 256, 256>>>(W0, HD, D0, 512, w0h, w0l); // 3
    convW_kernel<<<(HD * HD + 255) / 256, 256>>>(W1, HD, HD, HD, w1h, w1l);   // 4
    mma_gemm_kernel<<<gg, 256, GSMEM>>>(xh, xl, LDX, w0h, w0l, 512, b0,
                                        h1h, h1l, nullptr, 0);                // 5
    mma_gemm_kernel<<<gg, 256, GSMEM>>>(h1h, h1l, HD, w1h, w1l, HD, b1,
                                        h2h, h2l, nullptr, 0);                // 6
    convW_kernel<<<(HD * HD + 255) / 256, 256>>>(W2, HD, HD, HD, w2h, w2l);   // 7
    mma_gemm_kernel<<<gg, 256, GSMEM>>>(h2h, h2l, HD, w2h, w2l, HD, b2,
                                        nullptr, nullptr, fin, 1);            // 8
    final_kernel<<<NQ / 8, 256>>>(fin, W3, b3, out);                          // 9
}

// round 7
// speedup vs baseline: 1.3084x; 1.2704x over previous
#include <cuda_runtime.h>
#include <cuda_bf16.h>
#include <math.h>
#include <cstdint>

#define NQ   24576        // R*S
#define SS   48
#define MP   4096
#define LDX  512          // padded feature stride (D0=511 + 1 zero col)
#define D0   511
#define HD   256

// ---------------- scratch (static device globals; no runtime alloc) ----------
__device__ float g_X [NQ * LDX];   // 50 MB feature matrix (fp32)
__device__ float g_h1[NQ * HD];
__device__ float g_h2[NQ * HD];
// pre-split weights (bf16 hi/lo), W0 padded K 511 -> 512
__device__ __nv_bfloat16 g_w0h[HD * 512], g_w0l[HD * 512];
__device__ __nv_bfloat16 g_w1h[HD * HD],  g_w1l[HD * HD];
__device__ __nv_bfloat16 g_w2h[HD * HD],  g_w2l[HD * HD];
// spatial grid
__device__ int    g_start[1001];
__device__ float4 g_sorted[MP];    // cell-ordered particles, .w = index bits

// ============================ helpers ========================================
__device__ __forceinline__ uint32_t smem_u32(const void* p) {
    uint32_t a;
    asm("{ .reg .u64 t; cvta.to.shared.u64 t, %1; cvt.u32.u64 %0, t; }"
        : "=r"(a) : "l"(p));
    return a;
}
__device__ __forceinline__ void ldm_x4(uint32_t* r, uint32_t addr) {
    asm volatile("ldmatrix.sync.aligned.m8n8.x4.shared.b16 {%0,%1,%2,%3}, [%4];"
        : "=r"(r[0]), "=r"(r[1]), "=r"(r[2]), "=r"(r[3]) : "r"(addr));
}
__device__ __forceinline__ void ldm_x2(uint32_t* r, uint32_t addr) {
    asm volatile("ldmatrix.sync.aligned.m8n8.x2.shared.b16 {%0,%1}, [%2];"
        : "=r"(r[0]), "=r"(r[1]) : "r"(addr));
}
__device__ __forceinline__ void mma_bf16(float* d, const uint32_t* a, const uint32_t* b) {
    asm volatile("mma.sync.aligned.m16n8k16.row.col.f32.bf16.bf16.f32 "
        "{%0,%1,%2,%3}, {%4,%5,%6,%7}, {%8,%9}, {%0,%1,%2,%3};"
        : "+f"(d[0]), "+f"(d[1]), "+f"(d[2]), "+f"(d[3])
        : "r"(a[0]), "r"(a[1]), "r"(a[2]), "r"(a[3]), "r"(b[0]), "r"(b[1]));
}
__device__ __forceinline__ uint32_t swz(uint32_t off) {
    return off ^ ((off >> 3) & 0x70);
}
__device__ __forceinline__ int cell_of(float x, float y, float z) {
    int cx = min(max(__float2int_rd(x * 10.0f), 0), 9);
    int cy = min(max(__float2int_rd(y * 10.0f), 0), 9);
    int cz = min(max(__float2int_rd(z * 10.0f), 0), 9);
    return cx + 10 * cy + 100 * cz;
}

// ---------------- grid build: ONE CTA does count + scan + scatter --------------
__global__ void __launch_bounds__(1024)
gridbuild_kernel(const float* __restrict__ pp)
{
    __shared__ int scnt[1000];
    __shared__ int ssc[1024];
    const int t = threadIdx.x;
    if (t < 1000) scnt[t] = 0;
    __syncthreads();
    for (int i = t; i < MP; i += 1024)
        atomicAdd(&scnt[cell_of(pp[3*i], pp[3*i+1], pp[3*i+2])], 1);
    __syncthreads();
    int v = (t < 1000) ? scnt[t] : 0;
    ssc[t] = v;
    __syncthreads();
    for (int d = 1; d < 1024; d <<= 1) {
        int u = (t >= d) ? ssc[t - d] : 0;
        __syncthreads();
        ssc[t] += u;
        __syncthreads();
    }
    if (t < 1000) { g_start[t] = ssc[t] - v; scnt[t] = ssc[t] - v; }
    if (t == 0)   g_start[1000] = MP;
    __syncthreads();
    for (int i = t; i < MP; i += 1024) {
        float x = pp[3*i], y = pp[3*i+1], z = pp[3*i+2];
        int c = cell_of(x, y, z);
        int pos = atomicAdd(&scnt[c], 1);
        g_sorted[pos] = make_float4(x, y, z, __int_as_float(i));
    }
}

// ---------------- posenc via double-angle recurrence ---------------------------
template<int C, int F>
__device__ __forceinline__ void posenc_write(float* dst, const float* v)
{
    float s[C], c[C];
    #pragma unroll
    for (int i = 0; i < C; i++) { dst[i] = v[i]; sincosf(v[i], &s[i], &c[i]); }
    #pragma unroll
    for (int f = 0; f < F; f++) {
        #pragma unroll
        for (int i = 0; i < C; i++) {
            dst[C + f*2*C + i]     = s[i];
            dst[C + f*2*C + C + i] = c[i];
        }
        if (f + 1 < F) {
            #pragma unroll
            for (int i = 0; i < C; i++) {
                float ns = 2.0f * s[i] * c[i];
                float nc = fmaf(-2.0f * s[i], s[i], 1.0f);
                s[i] = ns; c[i] = nc;
            }
        }
    }
}

// ---------------- feature kernel: grid ball query + embeddings -----------------
// dyn smem: spts float4[4096] | sstart int[1001] | SB float[128][65]
#define OF_START 65536
#define OF_SB    (OF_START + 4016)
#define FSMEM    (OF_SB + 128 * 65 * 4)

__global__ void __launch_bounds__(128)
feature_kernel(const float* __restrict__ points,
               const float* __restrict__ normals,
               const float* __restrict__ rays,
               const float* __restrict__ ro)
{
    extern __shared__ char fsm[];
    float4* spts   = (float4*)fsm;
    int*    sstart = (int*)(fsm + OF_START);
    float (*SB)[65] = (float(*)[65])(fsm + OF_SB);

    const int tid = threadIdx.x;
    for (int i = tid; i < MP;   i += 128) spts[i]   = g_sorted[i];
    for (int i = tid; i < 1001; i += 128) sstart[i] = g_start[i];
    __syncthreads();

    const int gid = blockIdx.x * 128 + tid;
    const float qx = points[3*gid+0], qy = points[3*gid+1], qz = points[3*gid+2];

    const float R2  = (float)(0.1 * 0.1);   // fp64-computed threshold bits
    const float RAD = 0.1f;

    int cand[64];
    int cnt = 0;
    {
        int cx = min(max(__float2int_rd(qx * 10.0f), 0), 9);
        int cy = min(max(__float2int_rd(qy * 10.0f), 0), 9);
        int cz = min(max(__float2int_rd(qz * 10.0f), 0), 9);
        int x0 = max(cx-1,0), x1 = min(cx+1,9);
        int y0 = max(cy-1,0), y1 = min(cy+1,9);
        int z0 = max(cz-1,0), z1 = min(cz+1,9);
        for (int zz = z0; zz <= z1; zz++)
        for (int yy = y0; yy <= y1; yy++)
        for (int xx = x0; xx <= x1; xx++) {
            int c  = xx + 10*yy + 100*zz;
            int s0 = sstart[c], s1 = sstart[c+1];
            for (int i = s0; i < s1; i++) {
                float4 p = spts[i];
                float dx = p.x - qx, dy = p.y - qy, dz = p.z - qz;
                float d2 = dx*dx + dy*dy + dz*dz;
                if (d2 < R2 && cnt < 64)
                    cand[cnt++] = (__float_as_int(p.w) << 12) | i;
            }
        }
    }
    // sort ascending by original index -> first-k-by-index semantics
    for (int i = 1; i < cnt; i++) {
        int v = cand[i], j = i - 1;
        while (j >= 0 && cand[j] > v) { cand[j+1] = cand[j]; j--; }
        cand[j+1] = v;
    }
    const int kk = min(cnt, 16);
    float nx[16], ny[16], nz[16], nd[16];
    for (int k = 0; k < kk; k++) {
        float4 p = spts[cand[k] & 4095];
        float dx = p.x - qx, dy = p.y - qy, dz = p.z - qz;
        nx[k] = p.x; ny[k] = p.y; nz[k] = p.z;
        nd[k] = dx*dx + dy*dy + dz*dz;
    }

    float qn = sqrtf(qx*qx + qy*qy + qz*qz);
    float t0 = qn / RAD;
    float w0 = fmaxf(1.0f - t0*t0*t0, 0.0f);

    float density = 0.0f, smx = 0.0f, smy = 0.0f, smz = 0.0f;
    for (int k = 0; k < 16; k++) {
        if (k < kk) {
            float dn = sqrtf(nd[k]);
            float tt = dn / RAD;
            float w  = fmaxf(1.0f - tt*tt*tt, 0.0f);
            density += w;
            smx += w * nx[k]; smy += w * ny[k]; smz += w * nz[k];
        } else {
            density += w0;
        }
    }

    int   num_nn = 0;
    float sdx = 0.0f, sdy = 0.0f, sdz = 0.0f;
    for (int k = 0; k < kk; k++) {
        if (nd[k] != 0.0f) {
            num_nn++;
            sdx += nx[k] - qx; sdy += ny[k] - qy; sdz += nz[k] - qz;
        }
    }
    float inv = (float)num_nn + 1e-12f;
    float mx = sdx / inv, my = sdy / inv, mz = sdz / inv;
    float vx = 0.0f, vy = 0.0f, vz = 0.0f;
    for (int k = 0; k < kk; k++) {
        if (nd[k] != 0.0f) {
            float ex = (nx[k] - qx) - mx;
            float ey = (ny[k] - qy) - my;
            float ez = (nz[k] - qz) - mz;
            vx += ex*ex; vy += ey*ey; vz += ez*ez;
        }
    }
    vx /= inv; vy /= inv; vz /= inv;

    float dinv = density + 1e-12f;
    float spx = smx / dinv, spy = smy / dinv, spz = smz / dinv;
    float dirx = spx - ro[0], diry = spy - ro[1], dirz = spz - ro[2];
    float dl = sqrtf(dirx*dirx + diry*diry + dirz*dirz);
    dirx /= dl; diry /= dl; dirz /= dl;

    // ---- build the row in a per-thread buffer (local memory; coalesced) ----
    float rowbuf[256];
    float q3[3]  = {qx, qy, qz};       posenc_write<3,10>(rowbuf + 0,   q3);
    float d1[1]  = {density};          posenc_write<1,4> (rowbuf + 63,  d1);
    float sp3[3] = {spx, spy, spz};    posenc_write<3,10>(rowbuf + 72,  sp3);
    float v3[3]  = {vx, vy, vz};       posenc_write<3,10>(rowbuf + 135, v3);
    int r = gid / SS;
    float rd[3]  = {rays[6*r+3], rays[6*r+4], rays[6*r+5]};
    posenc_write<3,4>(rowbuf + 198, rd);
    float dd[3]  = {dirx, diry, dirz}; posenc_write<3,4> (rowbuf + 225, dd);
    rowbuf[252] = normals[3*gid+0];
    rowbuf[253] = normals[3*gid+1];
    rowbuf[254] = normals[3*gid+2];
    rowbuf[255] = 0.0f;   // col 255 placeholder (copy_fv overwrites it later)

    // ---- coalesced flush: local -> smem transpose tile -> global ----
    const int rowGlobalBase = blockIdx.x * 128;
    __syncthreads();   // spts/sstart reads done; SB region reuse safe
    #pragma unroll
    for (int c0 = 0; c0 < 256; c0 += 64) {
        #pragma unroll
        for (int c = 0; c < 64; c++) SB[tid][c] = rowbuf[c0 + c];
        __syncthreads();
        #pragma unroll
        for (int i = 0; i < 64; i++) {
            int idx = tid + i * 128;
            int rr = idx >> 6, cc = idx & 63;
            g_X[(size_t)(rowGlobalBase + rr) * LDX + c0 + cc] = SB[rr][cc];
        }
        __syncthreads();
    }
}

// ---------------- coalesced copy of feature_vectors into X[:,255:511] ----------
__global__ void __launch_bounds__(256)
copy_fv_kernel(const float* __restrict__ fv)
{
    int i = blockIdx.x * blockDim.x + threadIdx.x;
    if (i < NQ * HD) {
        int row = i >> 8;
        int col = i & 255;
        g_X[(size_t)row * LDX + 255 + col] = fv[i];
        if (col == 0) g_X[(size_t)row * LDX + 511] = 0.0f;   // pad column
    }
}

// ---------------- weight split: fp32 -> bf16 hi/lo, K padded to Kp -------------
__global__ void __launch_bounds__(256)
convW_kernel(const float* __restrict__ W, int N, int K, int Kp,
             __nv_bfloat16* __restrict__ Wh, __nv_bfloat16* __restrict__ Wl)
{
    int i = blockIdx.x * 256 + threadIdx.x;
    if (i >= N * Kp) return;
    int n = i / Kp, k = i - n * Kp;
    float v = (k < K) ? W[(size_t)n * K + k] : 0.0f;
    __nv_bfloat16 h = __float2bfloat16(v);
    float r = v - __bfloat162float(h);
    Wh[i] = h;
    Wl[i] = __float2bfloat16(r);
}

// ================= warp-mma split-bf16 GEMM: C = relu(A @ W^T + b) =============
// A fp32 [NQ, lda]; Wh/Wl bf16 [256, Kp]; C fp32 [NQ, 256].
// Block tile 128m x 128n x 32k, 8 warps (4m x 2n), warp tile 32m x 64n.
// (Round-3 measured-best GEMM, verbatim.)
#define BM 128
#define BN 128
#define STAGE 32768            // A 16KB + B 16KB per stage
#define GSMEM (2 * STAGE + 512)

__device__ __forceinline__ void cvt8_bf16(const float* a, uint4& hv, uint4& lv)
{
    uint32_t hw[4], lw[4];
    #pragma unroll
    for (int e = 0; e < 4; e++) {
        __nv_bfloat16 h0 = __float2bfloat16(a[2*e]);
        __nv_bfloat16 h1 = __float2bfloat16(a[2*e+1]);
        float r0 = a[2*e]   - __bfloat162float(h0);
        float r1 = a[2*e+1] - __bfloat162float(h1);
        __nv_bfloat16 l0 = __float2bfloat16(r0);
        __nv_bfloat16 l1 = __float2bfloat16(r1);
        hw[e] = (uint32_t)__bfloat16_as_ushort(h0) | ((uint32_t)__bfloat16_as_ushort(h1) << 16);
        lw[e] = (uint32_t)__bfloat16_as_ushort(l0) | ((uint32_t)__bfloat16_as_ushort(l1) << 16);
    }
    hv = make_uint4(hw[0], hw[1], hw[2], hw[3]);
    lv = make_uint4(lw[0], lw[1], lw[2], lw[3]);
}

__global__ void __launch_bounds__(256)
mma_gemm_kernel(const float* __restrict__ A, int lda,
                const __nv_bfloat16* __restrict__ Bh,
                const __nv_bfloat16* __restrict__ Bl,
                int Kp,
                const float* __restrict__ bias,
                float* __restrict__ C)
{
    extern __shared__ char gsm[];
    const uint32_t sbase = smem_u32(gsm);
    float* sbias = (float*)(gsm + 2 * STAGE);

    const int tid  = threadIdx.x;
    const int wid  = tid >> 5;
    const int lane = tid & 31;
    const int wm   = wid & 3;          // 4 warps in m
    const int wn   = wid >> 2;         // 2 warps in n
    const int rowBase = blockIdx.x * BM;
    const int colBase = blockIdx.y * BN;

    if (tid < 128) sbias[tid] = bias[colBase + tid];

    // staging index precompute
    const int arow = tid >> 2, acp = tid & 3;            // A: 2 units via +64 rows
    const int brow = tid >> 3, bc  = tid & 7;            // B: 4 units via +32 rows

    float acc[2][8][4];
    #pragma unroll
    for (int mi = 0; mi < 2; mi++)
        #pragma unroll
        for (int ni = 0; ni < 8; ni++)
            #pragma unroll
            for (int e = 0; e < 4; e++) acc[mi][ni][e] = 0.0f;

    const int T = Kp / 32;

    // ---- stage tile 0 ----
    {
        const int k0 = 0;
        #pragma unroll
        for (int i = 0; i < 2; i++) {
            int row = arow + i * 64;
            const float* s = A + (size_t)(rowBase + row) * lda + k0 + acp * 8;
            float av[8];
            *(float4*)&av[0] = *(const float4*)s;
            *(float4*)&av[4] = *(const float4*)(s + 4);
            uint4 hv, lv; cvt8_bf16(av, hv, lv);
            uint32_t off = (uint32_t)(row << 7) + (uint32_t)(acp << 4);
            *(uint4*)(gsm + swz(off))      = hv;
            *(uint4*)(gsm + swz(off + 64)) = lv;
        }
        #pragma unroll
        for (int i = 0; i < 4; i++) {
            int row = brow + i * 32;
            const __nv_bfloat16* src = (bc < 4)
                ? Bh + (size_t)(colBase + row) * Kp + k0 + bc * 8
                : Bl + (size_t)(colBase + row) * Kp + k0 + (bc - 4) * 8;
            uint4 v = *(const uint4*)src;
            uint32_t off = (uint32_t)(row << 7) + (uint32_t)(bc << 4);
            *(uint4*)(gsm + 16384 + swz(off)) = v;
        }
    }
    __syncthreads();

    for (int t = 0; t < T; t++) {
        const int buf = t & 1;
        // ---- prefetch next tile into registers ----
        float4 pa[2][2];
        uint4  pb[4];
        if (t + 1 < T) {
            const int k0 = (t + 1) * 32;
            #pragma unroll
            for (int i = 0; i < 2; i++) {
                int row = arow + i * 64;
                const float* s = A + (size_t)(rowBase + row) * lda + k0 + acp * 8;
                pa[i][0] = *(const float4*)s;
                pa[i][1] = *(const float4*)(s + 4);
            }
            #pragma unroll
            for (int i = 0; i < 4; i++) {
                int row = brow + i * 32;
                const __nv_bfloat16* src = (bc < 4)
                    ? Bh + (size_t)(colBase + row) * Kp + k0 + bc * 8
                    : Bl + (size_t)(colBase + row) * Kp + k0 + (bc - 4) * 8;
                pb[i] = *(const uint4*)src;
            }
        }

        // ---- compute current tile ----
        const uint32_t aB = sbase + buf * STAGE;
        const uint32_t bB = aB + 16384;
        #pragma unroll
        for (int ks = 0; ks < 2; ks++) {
            uint32_t bf[8][2][2];
            #pragma unroll
            for (int ni = 0; ni < 8; ni++)
                #pragma unroll
                for (int h = 0; h < 2; h++) {
                    int r  = wn * 64 + ni * 8 + (lane & 7);
                    int ch = h * 4 + ks * 2 + ((lane >> 3) & 1);
                    ldm_x2(bf[ni][h], bB + swz((uint32_t)(r << 7) + (uint32_t)(ch << 4)));
                }
            #pragma unroll
            for (int mi = 0; mi < 2; mi++) {
                uint32_t afh[4], afl[4];
                {
                    int r  = wm * 32 + mi * 16 + (lane & 15);
                    int c0 = ks * 2 + (lane >> 4);
                    ldm_x4(afh, aB + swz((uint32_t)(r << 7) + (uint32_t)(c0 << 4)));
                    ldm_x4(afl, aB + swz((uint32_t)(r << 7) + (uint32_t)((c0 + 4) << 4)));
                }
                #pragma unroll
                for (int ni = 0; ni < 8; ni++) {
                    mma_bf16(acc[mi][ni], afh, bf[ni][0]);  // Ah*Bh
                    mma_bf16(acc[mi][ni], afh, bf[ni][1]);  // Ah*Bl
                    mma_bf16(acc[mi][ni], afl, bf[ni][0]);  // Al*Bh
                }
            }
        }

        // ---- store prefetched tile ----
        if (t + 1 < T) {
            char* dst = gsm + (buf ^ 1) * STAGE;
            #pragma unroll
            for (int i = 0; i < 2; i++) {
                int row = arow + i * 64;
                float av[8];
                *(float4*)&av[0] = pa[i][0];
                *(float4*)&av[4] = pa[i][1];
                uint4 hv, lv; cvt8_bf16(av, hv, lv);
                uint32_t off = (uint32_t)(row << 7) + (uint32_t)(acp << 4);
                *(uint4*)(dst + swz(off))      = hv;
                *(uint4*)(dst + swz(off + 64)) = lv;
            }
            #pragma unroll
            for (int i = 0; i < 4; i++) {
                int row = brow + i * 32;
                uint32_t off = (uint32_t)(row << 7) + (uint32_t)(bc << 4);
                *(uint4*)(dst + 16384 + swz(off)) = pb[i];
            }
        }
        __syncthreads();
    }

    // ---- epilogue: bias + relu + store ----
    #pragma unroll
    for (int mi = 0; mi < 2; mi++)
        #pragma unroll
        for (int ni = 0; ni < 8; ni++) {
            int m  = rowBase + wm * 32 + mi * 16 + (lane >> 2);
            int nl = wn * 64 + ni * 8 + ((lane & 3) << 1);
            int n  = colBase + nl;
            float b0 = sbias[nl], b1 = sbias[nl + 1];
            float2 v0, v1;
            v0.x = fmaxf(acc[mi][ni][0] + b0, 0.0f);
            v0.y = fmaxf(acc[mi][ni][1] + b1, 0.0f);
            v1.x = fmaxf(acc[mi][ni][2] + b0, 0.0f);
            v1.y = fmaxf(acc[mi][ni][3] + b1, 0.0f);
            *(float2*)(C + (size_t)m * HD + n)       = v0;
            *(float2*)(C + (size_t)(m + 8) * HD + n) = v1;
        }
}

// ---------------- final layer: out = sigmoid(X @ W3^T + b3), W3 [3,256] --------
__global__ void __launch_bounds__(256)
final_kernel(const float* __restrict__ Xin,
             const float* __restrict__ W3,
             const float* __restrict__ b3,
             float* __restrict__ out)
{
    __shared__ float w[3][256];
    __shared__ float bb[3];
    const int tid = threadIdx.x;
    for (int i = tid; i < 768; i += 256) w[i >> 8][i & 255] = W3[i];
    if (tid < 3) bb[tid] = b3[tid];
    __syncthreads();

    const int warp = tid >> 5, lane = tid & 31;
    const int row = blockIdx.x * 8 + warp;
    const float* xr = Xin + (size_t)row * HD;

    float a0 = 0.0f, a1 = 0.0f, a2 = 0.0f;
    #pragma unroll
    for (int i = lane; i < HD; i += 32) {
        float xv = xr[i];
        a0 = fmaf(xv, w[0][i], a0);
        a1 = fmaf(xv, w[1][i], a1);
        a2 = fmaf(xv, w[2][i], a2);
    }
    #pragma unroll
    for (int off = 16; off; off >>= 1) {
        a0 += __shfl_xor_sync(0xffffffffu, a0, off);
        a1 += __shfl_xor_sync(0xffffffffu, a1, off);
        a2 += __shfl_xor_sync(0xffffffffu, a2, off);
    }
    if (lane == 0) {
        out[row * 3 + 0] = 1.0f / (1.0f + expf(-(a0 + bb[0])));
        out[row * 3 + 1] = 1.0f / (1.0f + expf(-(a1 + bb[1])));
        out[row * 3 + 2] = 1.0f / (1.0f + expf(-(a2 + bb[2])));
    }
}

// ---------------- launch --------------------------------------------------------
extern "C" void kernel_launch(void* const* d_in, const int* in_sizes, int n_in,
                              void* d_out, int out_size)
{
    const float* points  = (const float*)d_in[0];
    const float* normals = (const float*)d_in[1];
    const float* fv      = (const float*)d_in[3];
    const float* pp      = (const float*)d_in[5];
    const float* rays    = (const float*)d_in[6];
    const float* ro      = (const float*)d_in[7];
    const float* W0 = (const float*)d_in[8];
    const float* b0 = (const float*)d_in[9];
    const float* W1 = (const float*)d_in[10];
    const float* b1 = (const float*)d_in[11];
    const float* W2 = (const float*)d_in[12];
    const float* b2 = (const float*)d_in[13];
    const float* W3 = (const float*)d_in[14];
    const float* b3 = (const float*)d_in[15];
    float* out = (float*)d_out;

    float *gX, *gh1, *gh2;
    __nv_bfloat16 *w0h, *w0l, *w1h, *w1l, *w2h, *w2l;
    cudaGetSymbolAddress((void**)&gX,  g_X);
    cudaGetSymbolAddress((void**)&gh1, g_h1);
    cudaGetSymbolAddress((void**)&gh2, g_h2);
    cudaGetSymbolAddress((void**)&w0h, g_w0h);
    cudaGetSymbolAddress((void**)&w0l, g_w0l);
    cudaGetSymbolAddress((void**)&w1h, g_w1h);
    cudaGetSymbolAddress((void**)&w1l, g_w1l);
    cudaGetSymbolAddress((void**)&w2h, g_w2h);
    cudaGetSymbolAddress((void**)&w2l, g_w2l);

    cudaFuncSetAttribute(feature_kernel,
                         cudaFuncAttributeMaxDynamicSharedMemorySize, FSMEM);
    cudaFuncSetAttribute(mma_gemm_kernel,
                         cudaFuncAttributeMaxDynamicSharedMemorySize, GSMEM);

    dim3 gg(NQ / BM, HD / BN);   // 192 x 2

    gridbuild_kernel<<<1, 1024>>>(pp);                                        // 0
    feature_kernel<<<NQ / 128, 128, FSMEM>>>(points, normals, rays, ro);      // 1
    copy_fv_kernel<<<(NQ * HD) / 256, 256>>>(fv);                             // 2
    convW_kernel<<<(HD * 512 + 255) / 256, 256>>>(W0, HD, D0, 512, w0h, w0l); // 3
    convW_kernel<<<(HD * HD + 255) / 256, 256>>>(W1, HD, HD, HD, w1h, w1l);   // 4
    mma_gemm_kernel<<<gg, 256, GSMEM>>>(gX,  LDX, w0h, w0l, 512, b0, gh1);    // 5
    mma_gemm_kernel<<<gg, 256, GSMEM>>>(gh1, HD,  w1h, w1l, HD,  b1, gh2);    // 6
    convW_kernel<<<(HD * HD + 255) / 256, 256>>>(W2, HD, HD, HD, w2h, w2l);   // 7
    mma_gemm_kernel<<<gg, 256, GSMEM>>>(gh2, HD,  w2h, w2l, HD,  b2, gh1);    // 8
    final_kernel<<<NQ / 8, 256>>>(gh1, W3, b3, out);                          // 9
}